// round 1
// baseline (speedup 1.0000x reference)
#include <cuda_runtime.h>
#include <math.h>

// ---------------- device scratch (no allocations allowed) ----------------
static __device__ float g_sums[32 * 25];
static __device__ float g_gate[32 * 25];
static __device__ int   g_chan[32 * 25];

// =========================================================================
// Kernel A: fused dwconv7 + bias + exact GELU + region-weighted spatial sum
// (the dwconv3 + mean is collapsed algebraically into 9 region weights)
// One block per (b,c) map. 256 threads = 64 col-groups x 4 row bands.
// Each thread: 4 output columns, 63 output rows, 7-deep ring accumulators
// with fully static slot indices (rows processed in groups of 7).
// =========================================================================
__global__ __launch_bounds__(256, 1)
void conv_reduce_kernel(const float* __restrict__ x,
                        const float* __restrict__ w7,
                        const float* __restrict__ b7,
                        const float* __restrict__ w3)
{
    __shared__ float sw[49];
    __shared__ float sWcat[9];   // [rowcat*3 + colcat]
    __shared__ float sbias;
    __shared__ float sred[256];

    const int m = blockIdx.x;       // b*25 + c
    const int c = m % 25;
    const int tid = threadIdx.x;

    if (tid < 49) sw[tid] = w7[c * 49 + tid];
    if (tid == 49) sbias = b7[c];
    if (tid == 50) {
        // conv3-sum region weights: W(rowcat,colcat) = sum of w3 taps valid there
        const float* w3c = w3 + c * 9;
        float Sc[3][3];
        #pragma unroll
        for (int a = 0; a < 3; a++) {
            float v0 = w3c[a*3+0], v1 = w3c[a*3+1], v2 = w3c[a*3+2];
            Sc[a][0] = v0 + v1;        // col 0   (b in {0,1})
            Sc[a][1] = v0 + v1 + v2;   // interior
            Sc[a][2] = v1 + v2;        // col 251 (b in {1,2})
        }
        #pragma unroll
        for (int cc = 0; cc < 3; cc++) {
            sWcat[0*3+cc] = Sc[0][cc] + Sc[1][cc];              // row 0
            sWcat[1*3+cc] = Sc[0][cc] + Sc[1][cc] + Sc[2][cc];  // interior
            sWcat[2*3+cc] = Sc[1][cc] + Sc[2][cc];              // row 251
        }
    }
    __syncthreads();

    const int cg   = tid & 63;
    const int band = tid >> 6;
    float gsum = 0.f;

    if (cg < 63) {
        float w[49];
        #pragma unroll
        for (int k = 0; k < 49; k++) w[k] = sw[k];
        const float bias = sbias;

        const int q0 = cg * 4;
        float wv0[4], wv1[4], wv2[4];
        #pragma unroll
        for (int t = 0; t < 4; t++) {
            int q   = q0 + t;
            int cat = (q == 0) ? 0 : ((q == 251) ? 2 : 1);
            wv0[t] = sWcat[0*3 + cat];
            wv1[t] = sWcat[1*3 + cat];
            wv2[t] = sWcat[2*3 + cat];
        }

        const int lo = band * 63;                 // lo % 7 == 0
        const float* __restrict__ xm = x + (size_t)m * 65536;

        float acc[7][4];
        #pragma unroll
        for (int s = 0; s < 7; s++)
            #pragma unroll
            for (int t = 0; t < 4; t++) acc[s][t] = 0.f;

        for (int it = 0; it < 10; ++it) {
            #pragma unroll
            for (int u = 0; u < 7; u++) {
                const int r = lo - 1 + it * 7 + u;   // input row (r % 7 == (u+6)%7)
                float xw[10];
                if (r >= 0 && r < 256) {
                    const float* row = xm + r * 256;
                    xw[0] = (q0 > 0) ? row[q0 - 1] : 0.f;
                    float4 v0 = *reinterpret_cast<const float4*>(row + q0);
                    float4 v1 = *reinterpret_cast<const float4*>(row + q0 + 4);
                    xw[1]=v0.x; xw[2]=v0.y; xw[3]=v0.z; xw[4]=v0.w;
                    xw[5]=v1.x; xw[6]=v1.y; xw[7]=v1.z; xw[8]=v1.w;
                    xw[9] = (q0 + 8 < 256) ? row[q0 + 8] : 0.f;
                } else {
                    #pragma unroll
                    for (int k = 0; k < 10; k++) xw[k] = 0.f;
                }

                // out row i = r+1-a  -> slot (u - a) mod 7 (compile-time)
                #pragma unroll
                for (int a = 0; a < 7; a++) {
                    const int s = (u - a + 7) % 7;
                    #pragma unroll
                    for (int dx = 0; dx < 7; dx++) {
                        const float wk = w[a * 7 + dx];
                        acc[s][0] = fmaf(xw[0 + dx], wk, acc[s][0]);
                        acc[s][1] = fmaf(xw[1 + dx], wk, acc[s][1]);
                        acc[s][2] = fmaf(xw[2 + dx], wk, acc[s][2]);
                        acc[s][3] = fmaf(xw[3 + dx], wk, acc[s][3]);
                    }
                }

                // retire out row i = r-5, slot (u+1)%7 (compile-time)
                {
                    const int off  = it * 7 + u - 6;       // i - lo
                    const int sret = (u + 1) % 7;
                    if (off >= 0 && off <= 62) {
                        const int i = lo + off;
                        const bool top = (i == 0), bot = (i == 251);
                        #pragma unroll
                        for (int t = 0; t < 4; t++) {
                            float h  = acc[sret][t] + bias;
                            float gl = 0.5f * h * (1.0f + erff(h * 0.7071067811865476f));
                            float ws = top ? wv0[t] : (bot ? wv2[t] : wv1[t]);
                            gsum = fmaf(gl, ws, gsum);
                        }
                    }
                    #pragma unroll
                    for (int t = 0; t < 4; t++) acc[sret][t] = 0.f;
                }
            }
        }
    }

    sred[tid] = gsum;
    __syncthreads();
    #pragma unroll
    for (int ofs = 128; ofs > 0; ofs >>= 1) {
        if (tid < ofs) sred[tid] += sred[tid + ofs];
        __syncthreads();
    }
    if (tid == 0) g_sums[m] = sred[0];
}

// =========================================================================
// Kernel B: per-batch MLP + sigmoid + gate + stable descending sort (top_k)
// One thread per batch element. Tiny.
// =========================================================================
__global__ void mlp_sort_kernel(const float* __restrict__ fc1w,
                                const float* __restrict__ fc1b,
                                const float* __restrict__ fc2w,
                                const float* __restrict__ fc2b,
                                float* __restrict__ out_idx)
{
    const int b = threadIdx.x;
    if (b >= 32) return;

    float g[25];
    #pragma unroll
    for (int c = 0; c < 25; c++)
        g[c] = g_sums[b * 25 + c] * (1.0f / 63504.0f);   // /252^2

    float hid[50];
    for (int j = 0; j < 50; j++) {
        float v = fc1b[j];
        #pragma unroll
        for (int c = 0; c < 25; c++) v = fmaf(g[c], fc1w[j * 25 + c], v);
        hid[j] = v > 0.f ? v : 0.f;
    }

    float sval[25], gv[25];
    for (int c = 0; c < 25; c++) {
        float z = fc2b[c];
        #pragma unroll
        for (int j = 0; j < 50; j++) z = fmaf(hid[j], fc2w[c * 50 + j], z);
        float s  = 1.0f / (1.0f + expf(-z));
        sval[c]  = s;
        float s2 = s * s;
        gv[c]    = s2 / (s2 + 1e-8f);
    }

    float key[25];
    #pragma unroll
    for (int c = 0; c < 25; c++) key[c] = sval[c];

    for (int r = 0; r < 25; r++) {
        int best = 0; float bv = key[0];
        for (int c = 1; c < 25; c++)
            if (key[c] > bv) { bv = key[c]; best = c; }   // strict > : stable (low idx first)
        key[best] = -1e30f;
        g_chan[b * 25 + r] = best;
        g_gate[b * 25 + r] = gv[best];
        out_idx[b * 25 + r] = (float)best;
    }
}

// =========================================================================
// Kernel C: gated channel-permuted gather into (x_selected | x_plug)
// ranks 0..9 -> x_selected, ranks 10..24 -> x_plug. float4 streaming.
// =========================================================================
__global__ __launch_bounds__(256)
void gather_kernel(const float* __restrict__ x, float* __restrict__ out)
{
    const int mp    = blockIdx.x;     // 0..6399
    const int map   = mp >> 3;        // (b,r)
    const int chunk = mp & 7;
    const int b = map / 25, r = map % 25;

    const int   ch = g_chan[map];
    const float gt = g_gate[map];

    const float4* __restrict__ src =
        reinterpret_cast<const float4*>(x + ((size_t)b * 25 + ch) * 65536);

    float* dbase;
    if (r < 10) dbase = out + ((size_t)b * 10 + r) * 65536;
    else        dbase = out + 20971520ull + ((size_t)b * 15 + (r - 10)) * 65536;
    float4* __restrict__ dst = reinterpret_cast<float4*>(dbase);

    const int base = chunk * 2048 + threadIdx.x;   // 16384 float4 per map, 8 chunks
    #pragma unroll
    for (int k = 0; k < 8; k++) {
        const int idx = base + k * 256;
        float4 v = src[idx];
        v.x *= gt; v.y *= gt; v.z *= gt; v.w *= gt;
        dst[idx] = v;
    }
}

// =========================================================================
extern "C" void kernel_launch(void* const* d_in, const int* in_sizes, int n_in,
                              void* d_out, int out_size)
{
    const float* x    = (const float*)d_in[0];
    const float* w7   = (const float*)d_in[1];
    const float* b7   = (const float*)d_in[2];
    const float* w3   = (const float*)d_in[3];
    const float* fc1w = (const float*)d_in[4];
    const float* fc1b = (const float*)d_in[5];
    const float* fc2w = (const float*)d_in[6];
    const float* fc2b = (const float*)d_in[7];
    float* out = (float*)d_out;

    conv_reduce_kernel<<<800, 256>>>(x, w7, b7, w3);
    mlp_sort_kernel<<<1, 32>>>(fc1w, fc1b, fc2w, fc2b, out + 52428800ull);
    gather_kernel<<<6400, 256>>>(x, out);
}

// round 2
// speedup vs baseline: 1.0595x; 1.0595x over previous
#include <cuda_runtime.h>
#include <math.h>

// ---------------- device scratch (no allocations allowed) ----------------
static __device__ float g_sums[32 * 25];
static __device__ float g_gate[32 * 25];
static __device__ int   g_chan[32 * 25];

// ---------------- packed f32x2 helpers (SASS FFMA2 path) ------------------
#define PACK2(p, lo, hi) \
    asm("mov.b64 %0, {%1, %2};" : "=l"(p) : "f"(lo), "f"(hi))
#define UNPACK2(lo, hi, p) \
    asm("mov.b64 {%0, %1}, %2;" : "=f"(lo), "=f"(hi) : "l"(p))
#define FMA2(acc, a, b) \
    asm("fma.rn.f32x2 %0, %1, %2, %0;" : "+l"(acc) : "l"(a), "l"(b))

// =========================================================================
// Kernel A: fused dwconv7 + bias + exact GELU + region-weighted spatial sum
// (the dwconv3 + mean is collapsed algebraically into 9 region weights)
// One block per (b,c) map. 256 threads = 64 col-groups x 4 row bands.
// Each thread: 4 output columns (2 packed f32x2 pairs), 63 output rows,
// 7-deep ring of packed accumulators with statically-resolved slots.
// =========================================================================
__global__ __launch_bounds__(256, 2)
void conv_reduce_kernel(const float* __restrict__ x,
                        const float* __restrict__ w7,
                        const float* __restrict__ b7,
                        const float* __restrict__ w3)
{
    __shared__ float sw[49];
    __shared__ float sWcat[9];   // [rowcat*3 + colcat]
    __shared__ float sbias;
    __shared__ float sred[256];

    const int m = blockIdx.x;       // b*25 + c
    const int c = m % 25;
    const int tid = threadIdx.x;

    if (tid < 49) sw[tid] = w7[c * 49 + tid];
    if (tid == 49) sbias = b7[c];
    if (tid == 50) {
        // conv3-sum region weights: W(rowcat,colcat) = sum of w3 taps valid there
        const float* w3c = w3 + c * 9;
        float Sc[3][3];
        #pragma unroll
        for (int a = 0; a < 3; a++) {
            float v0 = w3c[a*3+0], v1 = w3c[a*3+1], v2 = w3c[a*3+2];
            Sc[a][0] = v0 + v1;        // col 0
            Sc[a][1] = v0 + v1 + v2;   // interior
            Sc[a][2] = v1 + v2;        // col 251
        }
        #pragma unroll
        for (int cc = 0; cc < 3; cc++) {
            sWcat[0*3+cc] = Sc[0][cc] + Sc[1][cc];              // row 0
            sWcat[1*3+cc] = Sc[0][cc] + Sc[1][cc] + Sc[2][cc];  // interior
            sWcat[2*3+cc] = Sc[1][cc] + Sc[2][cc];              // row 251
        }
    }
    __syncthreads();

    const int cg   = tid & 63;
    const int band = tid >> 6;
    float gsum = 0.f;

    if (cg < 63) {
        float w[49];
        #pragma unroll
        for (int k = 0; k < 49; k++) w[k] = sw[k];
        const float bias = sbias;

        const int q0 = cg * 4;
        float wv0[4], wv1[4], wv2[4];
        #pragma unroll
        for (int t = 0; t < 4; t++) {
            int q   = q0 + t;
            int cat = (q == 0) ? 0 : ((q == 251) ? 2 : 1);
            wv0[t] = sWcat[0*3 + cat];
            wv1[t] = sWcat[1*3 + cat];
            wv2[t] = sWcat[2*3 + cat];
        }

        const int lo = band * 63;                 // lo % 7 == 0
        const float* __restrict__ xm = x + (size_t)m * 65536;

        // packed accumulators: [slot][pair], pair0 = cols 0-1, pair1 = cols 2-3
        unsigned long long accP[7][2];
        #pragma unroll
        for (int s = 0; s < 7; s++) { accP[s][0] = 0ull; accP[s][1] = 0ull; }

        for (int it = 0; it < 10; ++it) {
            #pragma unroll
            for (int u = 0; u < 7; u++) {
                const int r = lo - 1 + it * 7 + u;   // input row
                float xw[10];
                if (r >= 0 && r < 256) {
                    const float* row = xm + r * 256;
                    xw[0] = (q0 > 0) ? row[q0 - 1] : 0.f;
                    float4 v0 = *reinterpret_cast<const float4*>(row + q0);
                    float4 v1 = *reinterpret_cast<const float4*>(row + q0 + 4);
                    xw[1]=v0.x; xw[2]=v0.y; xw[3]=v0.z; xw[4]=v0.w;
                    xw[5]=v1.x; xw[6]=v1.y; xw[7]=v1.z; xw[8]=v1.w;
                    xw[9] = (q0 + 8 < 256) ? row[q0 + 8] : 0.f;
                } else {
                    #pragma unroll
                    for (int k = 0; k < 10; k++) xw[k] = 0.f;
                }

                // adjacent-pair packs of the window
                unsigned long long xp[9];
                #pragma unroll
                for (int i = 0; i < 9; i++) PACK2(xp[i], xw[i], xw[i + 1]);

                // out row i = r+1-a  -> slot (u - a) mod 7 (compile-time)
                #pragma unroll
                for (int a = 0; a < 7; a++) {
                    const int s = (u - a + 7) % 7;
                    #pragma unroll
                    for (int dx = 0; dx < 7; dx++) {
                        const float wk = w[a * 7 + dx];
                        unsigned long long wb;
                        PACK2(wb, wk, wk);
                        FMA2(accP[s][0], xp[dx],     wb);
                        FMA2(accP[s][1], xp[dx + 2], wb);
                    }
                }

                // retire out row i = r-5, slot (u+1)%7 (compile-time)
                {
                    const int off  = it * 7 + u - 6;       // i - lo
                    const int sret = (u + 1) % 7;
                    if (off >= 0 && off <= 62) {
                        const int i = lo + off;
                        const bool top = (i == 0), bot = (i == 251);
                        float hv[4];
                        UNPACK2(hv[0], hv[1], accP[sret][0]);
                        UNPACK2(hv[2], hv[3], accP[sret][1]);
                        #pragma unroll
                        for (int t = 0; t < 4; t++) {
                            float h  = hv[t] + bias;
                            float gl = 0.5f * h * (1.0f + erff(h * 0.7071067811865476f));
                            float ws = top ? wv0[t] : (bot ? wv2[t] : wv1[t]);
                            gsum = fmaf(gl, ws, gsum);
                        }
                    }
                    accP[sret][0] = 0ull;
                    accP[sret][1] = 0ull;
                }
            }
        }
    }

    sred[tid] = gsum;
    __syncthreads();
    #pragma unroll
    for (int ofs = 128; ofs > 0; ofs >>= 1) {
        if (tid < ofs) sred[tid] += sred[tid + ofs];
        __syncthreads();
    }
    if (tid == 0) g_sums[m] = sred[0];
}

// =========================================================================
// Kernel B: per-batch MLP + sigmoid + gate + stable descending sort (top_k)
// =========================================================================
__global__ void mlp_sort_kernel(const float* __restrict__ fc1w,
                                const float* __restrict__ fc1b,
                                const float* __restrict__ fc2w,
                                const float* __restrict__ fc2b,
                                float* __restrict__ out_idx)
{
    const int b = threadIdx.x;
    if (b >= 32) return;

    float g[25];
    #pragma unroll
    for (int c = 0; c < 25; c++)
        g[c] = g_sums[b * 25 + c] * (1.0f / 63504.0f);   // /252^2

    float hid[50];
    for (int j = 0; j < 50; j++) {
        float v = fc1b[j];
        #pragma unroll
        for (int c = 0; c < 25; c++) v = fmaf(g[c], fc1w[j * 25 + c], v);
        hid[j] = v > 0.f ? v : 0.f;
    }

    float sval[25], gv[25];
    for (int c = 0; c < 25; c++) {
        float z = fc2b[c];
        #pragma unroll
        for (int j = 0; j < 50; j++) z = fmaf(hid[j], fc2w[c * 50 + j], z);
        float s  = 1.0f / (1.0f + expf(-z));
        sval[c]  = s;
        float s2 = s * s;
        gv[c]    = s2 / (s2 + 1e-8f);
    }

    float key[25];
    #pragma unroll
    for (int c = 0; c < 25; c++) key[c] = sval[c];

    for (int r = 0; r < 25; r++) {
        int best = 0; float bv = key[0];
        for (int c = 1; c < 25; c++)
            if (key[c] > bv) { bv = key[c]; best = c; }   // strict > : stable
        key[best] = -1e30f;
        g_chan[b * 25 + r] = best;
        g_gate[b * 25 + r] = gv[best];
        out_idx[b * 25 + r] = (float)best;
    }
}

// =========================================================================
// Kernel C: gated channel-permuted gather into (x_selected | x_plug)
// Batched loads (MLP=8) + evict-first streaming hints both directions.
// =========================================================================
__global__ __launch_bounds__(256)
void gather_kernel(const float* __restrict__ x, float* __restrict__ out)
{
    const int mp    = blockIdx.x;     // 0..6399
    const int map   = mp >> 3;        // (b,r)
    const int chunk = mp & 7;
    const int b = map / 25, r = map % 25;

    const int   ch = g_chan[map];
    const float gt = g_gate[map];

    const float4* __restrict__ src =
        reinterpret_cast<const float4*>(x + ((size_t)b * 25 + ch) * 65536);

    float* dbase;
    if (r < 10) dbase = out + ((size_t)b * 10 + r) * 65536;
    else        dbase = out + 20971520ull + ((size_t)b * 15 + (r - 10)) * 65536;
    float4* __restrict__ dst = reinterpret_cast<float4*>(dbase);

    const int base = chunk * 2048 + threadIdx.x;   // 16384 float4 per map, 8 chunks

    float4 v[8];
    #pragma unroll
    for (int k = 0; k < 8; k++) v[k] = __ldcs(&src[base + k * 256]);
    #pragma unroll
    for (int k = 0; k < 8; k++) {
        v[k].x *= gt; v[k].y *= gt; v[k].z *= gt; v[k].w *= gt;
        __stcs(&dst[base + k * 256], v[k]);
    }
}

// =========================================================================
extern "C" void kernel_launch(void* const* d_in, const int* in_sizes, int n_in,
                              void* d_out, int out_size)
{
    const float* x    = (const float*)d_in[0];
    const float* w7   = (const float*)d_in[1];
    const float* b7   = (const float*)d_in[2];
    const float* w3   = (const float*)d_in[3];
    const float* fc1w = (const float*)d_in[4];
    const float* fc1b = (const float*)d_in[5];
    const float* fc2w = (const float*)d_in[6];
    const float* fc2b = (const float*)d_in[7];
    float* out = (float*)d_out;

    conv_reduce_kernel<<<800, 256>>>(x, w7, b7, w3);
    mlp_sort_kernel<<<1, 32>>>(fc1w, fc1b, fc2w, fc2b, out + 52428800ull);
    gather_kernel<<<6400, 256>>>(x, out);
}

// round 4
// speedup vs baseline: 1.0890x; 1.0278x over previous
#include <cuda_runtime.h>
#include <math.h>

// ---------------- device scratch (no allocations allowed) ----------------
static __device__ float g_sums[32 * 25];
static __device__ float g_gate[32 * 25];
static __device__ int   g_chan[32 * 25];

// =========================================================================
// Kernel A: fused dwconv7 + bias + exact GELU + region-weighted spatial sum
// (dwconv3 + mean collapsed algebraically into 9 region weights)
// fp32 FFMA path. One block per (b,c) map. 256 threads =
// 128 col-groups (126 active, 2 cols each) x 2 row bands (126 rows each).
// 7-deep ring accumulators with statically-resolved slots.
// Low register footprint (~80) -> 3 CTAs/SM.
// =========================================================================
__global__ __launch_bounds__(256, 3)
void conv_reduce_kernel(const float* __restrict__ x,
                        const float* __restrict__ w7,
                        const float* __restrict__ b7,
                        const float* __restrict__ w3)
{
    __shared__ float sw[49];
    __shared__ float sWcat[9];   // [rowcat*3 + colcat]
    __shared__ float sbias;
    __shared__ float sred[256];

    const int m = blockIdx.x;       // b*25 + c
    const int c = m % 25;
    const int tid = threadIdx.x;

    if (tid < 49) sw[tid] = w7[c * 49 + tid];
    if (tid == 49) sbias = b7[c];
    if (tid == 50) {
        const float* w3c = w3 + c * 9;
        float Sc[3][3];
        #pragma unroll
        for (int a = 0; a < 3; a++) {
            float v0 = w3c[a*3+0], v1 = w3c[a*3+1], v2 = w3c[a*3+2];
            Sc[a][0] = v0 + v1;        // col 0
            Sc[a][1] = v0 + v1 + v2;   // interior
            Sc[a][2] = v1 + v2;        // col 251
        }
        #pragma unroll
        for (int cc = 0; cc < 3; cc++) {
            sWcat[0*3+cc] = Sc[0][cc] + Sc[1][cc];              // row 0
            sWcat[1*3+cc] = Sc[0][cc] + Sc[1][cc] + Sc[2][cc];  // interior
            sWcat[2*3+cc] = Sc[1][cc] + Sc[2][cc];              // row 251
        }
    }
    __syncthreads();

    const int cg   = tid & 127;     // 0..127, active < 126
    const int band = tid >> 7;      // 0..1
    float gsum = 0.f;

    if (cg < 126) {
        float w[49];
        #pragma unroll
        for (int k = 0; k < 49; k++) w[k] = sw[k];
        const float bias = sbias;

        const int q0 = cg * 2;
        const int lo = band * 126;                // lo % 7 == 0
        const float* __restrict__ xm = x + (size_t)m * 65536;

        float acc[7][2];
        #pragma unroll
        for (int s = 0; s < 7; s++) { acc[s][0] = 0.f; acc[s][1] = 0.f; }

        for (int it = 0; it < 19; ++it) {
            #pragma unroll
            for (int u = 0; u < 7; u++) {
                const int r = lo - 1 + it * 7 + u;   // input row
                float xw[8];                          // cols q0-1 .. q0+6
                if (r >= 0 && r < 256) {
                    const float* row = xm + r * 256;
                    xw[0] = (q0 > 0) ? row[q0 - 1] : 0.f;
                    float2 a0 = *reinterpret_cast<const float2*>(row + q0);
                    float2 a1 = *reinterpret_cast<const float2*>(row + q0 + 2);
                    float2 a2 = *reinterpret_cast<const float2*>(row + q0 + 4);
                    xw[1]=a0.x; xw[2]=a0.y; xw[3]=a1.x; xw[4]=a1.y;
                    xw[5]=a2.x; xw[6]=a2.y;
                    xw[7] = (q0 + 6 < 256) ? row[q0 + 6] : 0.f;
                } else {
                    #pragma unroll
                    for (int k = 0; k < 8; k++) xw[k] = 0.f;
                }

                // out row i = r+1-a -> slot (u - a) mod 7 (compile-time)
                #pragma unroll
                for (int a = 0; a < 7; a++) {
                    const int s = (u - a + 7) % 7;
                    #pragma unroll
                    for (int dx = 0; dx < 7; dx++) {
                        const float wk = w[a * 7 + dx];
                        acc[s][0] = fmaf(xw[dx],     wk, acc[s][0]);
                        acc[s][1] = fmaf(xw[dx + 1], wk, acc[s][1]);
                    }
                }

                // retire out row i = r-5, slot (u+1)%7 (compile-time)
                {
                    const int off  = it * 7 + u - 6;     // i - lo
                    const int sret = (u + 1) % 7;
                    if (off >= 0 && off <= 125) {
                        const int i = lo + off;
                        const int rowcat = (i == 0) ? 0 : ((i == 251) ? 2 : 1);
                        #pragma unroll
                        for (int t = 0; t < 2; t++) {
                            const int q = q0 + t;
                            const int colcat = (q == 0) ? 0 : ((q == 251) ? 2 : 1);
                            float h  = acc[sret][t] + bias;
                            float gl = 0.5f * h * (1.0f + erff(h * 0.7071067811865476f));
                            gsum = fmaf(gl, sWcat[rowcat * 3 + colcat], gsum);
                        }
                    }
                    acc[sret][0] = 0.f;
                    acc[sret][1] = 0.f;
                }
            }
        }
    }

    sred[tid] = gsum;
    __syncthreads();
    #pragma unroll
    for (int ofs = 128; ofs > 0; ofs >>= 1) {
        if (tid < ofs) sred[tid] += sred[tid + ofs];
        __syncthreads();
    }
    if (tid == 0) g_sums[m] = sred[0];
}

// =========================================================================
// Kernel B: per-batch MLP + sigmoid + gate + stable top-k via rank compute.
// 32 blocks (one per batch) x 64 threads.
// =========================================================================
__global__ __launch_bounds__(64)
void mlp_sort_kernel(const float* __restrict__ fc1w,
                     const float* __restrict__ fc1b,
                     const float* __restrict__ fc2w,
                     const float* __restrict__ fc2b,
                     float* __restrict__ out_idx)
{
    const int b   = blockIdx.x;
    const int tid = threadIdx.x;

    __shared__ float sg[25];
    __shared__ float shid[50];
    __shared__ float ss[25];

    if (tid < 25)
        sg[tid] = g_sums[b * 25 + tid] * (1.0f / 63504.0f);   // /252^2
    __syncthreads();

    if (tid < 50) {
        float v = fc1b[tid];
        #pragma unroll
        for (int c = 0; c < 25; c++) v = fmaf(sg[c], fc1w[tid * 25 + c], v);
        shid[tid] = v > 0.f ? v : 0.f;
    }
    __syncthreads();

    float sv = 0.f, gv = 0.f;
    if (tid < 25) {
        float z = fc2b[tid];
        #pragma unroll
        for (int j = 0; j < 50; j++) z = fmaf(shid[j], fc2w[tid * 50 + j], z);
        sv = 1.0f / (1.0f + expf(-z));
        float s2 = sv * sv;
        gv = s2 / (s2 + 1e-8f);
        ss[tid] = sv;
    }
    __syncthreads();

    if (tid < 25) {
        // rank in stable descending order: strictly-greater, or equal at lower idx
        int rank = 0;
        #pragma unroll
        for (int c = 0; c < 25; c++) {
            float o = ss[c];
            rank += (o > sv) || (o == sv && c < tid);
        }
        g_chan[b * 25 + rank]  = tid;
        g_gate[b * 25 + rank]  = gv;
        out_idx[b * 25 + rank] = (float)tid;
    }
}

// =========================================================================
// Kernel C: gated channel-permuted gather into (x_selected | x_plug)
// 16 float4 per thread in flight; evict-first streaming hints both ways.
// =========================================================================
__global__ __launch_bounds__(256)
void gather_kernel(const float* __restrict__ x, float* __restrict__ out)
{
    const int mp    = blockIdx.x;     // 0..3199
    const int map   = mp >> 2;        // (b,r)
    const int chunk = mp & 3;
    const int b = map / 25, r = map % 25;

    const int   ch = g_chan[map];
    const float gt = g_gate[map];

    const float4* __restrict__ src =
        reinterpret_cast<const float4*>(x + ((size_t)b * 25 + ch) * 65536);

    float* dbase;
    if (r < 10) dbase = out + ((size_t)b * 10 + r) * 65536;
    else        dbase = out + 20971520ull + ((size_t)b * 15 + (r - 10)) * 65536;
    float4* __restrict__ dst = reinterpret_cast<float4*>(dbase);

    const int base = chunk * 4096 + threadIdx.x;  // 16384 f4 per map, 4 chunks

    float4 v[16];
    #pragma unroll
    for (int k = 0; k < 16; k++) v[k] = __ldcs(&src[base + k * 256]);
    #pragma unroll
    for (int k = 0; k < 16; k++) {
        v[k].x *= gt; v[k].y *= gt; v[k].z *= gt; v[k].w *= gt;
        __stcs(&dst[base + k * 256], v[k]);
    }
}

// =========================================================================
extern "C" void kernel_launch(void* const* d_in, const int* in_sizes, int n_in,
                              void* d_out, int out_size)
{
    const float* x    = (const float*)d_in[0];
    const float* w7   = (const float*)d_in[1];
    const float* b7   = (const float*)d_in[2];
    const float* w3   = (const float*)d_in[3];
    const float* fc1w = (const float*)d_in[4];
    const float* fc1b = (const float*)d_in[5];
    const float* fc2w = (const float*)d_in[6];
    const float* fc2b = (const float*)d_in[7];
    float* out = (float*)d_out;

    conv_reduce_kernel<<<800, 256>>>(x, w7, b7, w3);
    mlp_sort_kernel<<<32, 64>>>(fc1w, fc1b, fc2w, fc2b, out + 52428800ull);
    gather_kernel<<<3200, 256>>>(x, out);
}

// round 5
// speedup vs baseline: 1.2202x; 1.1205x over previous
#include <cuda_runtime.h>
#include <math.h>

// ---------------- device scratch (no allocations allowed) ----------------
static __device__ float g_sums[32 * 25];
static __device__ float g_gate[32 * 25];
static __device__ int   g_chan[32 * 25];

// =========================================================================
// Kernel A: fused dwconv7 + bias + exact GELU + region-weighted spatial sum
// (dwconv3 + mean collapsed algebraically into 9 region weights)
// fp32 FFMA, fully BRANCH-FREE inner loop (clamped rows + FSEL zeroing)
// so ptxas can batch LDGs across unrolled rows and hide latency.
// One block per (b,c) map: 256 threads = 64 col-groups x 4 row bands,
// 4 output cols/thread, 7-deep ring accumulators, static slots.
// =========================================================================
__global__ __launch_bounds__(256, 2)
void conv_reduce_kernel(const float* __restrict__ x,
                        const float* __restrict__ w7,
                        const float* __restrict__ b7,
                        const float* __restrict__ w3)
{
    __shared__ float sw[49];
    __shared__ float sWcat[9];   // [rowcat*3 + colcat]
    __shared__ float sbias;
    __shared__ float sred[256];

    const int m = blockIdx.x;       // b*25 + c
    const int c = m % 25;
    const int tid = threadIdx.x;

    if (tid < 49) sw[tid] = w7[c * 49 + tid];
    if (tid == 49) sbias = b7[c];
    if (tid == 50) {
        const float* w3c = w3 + c * 9;
        float Sc[3][3];
        #pragma unroll
        for (int a = 0; a < 3; a++) {
            float v0 = w3c[a*3+0], v1 = w3c[a*3+1], v2 = w3c[a*3+2];
            Sc[a][0] = v0 + v1;        // col 0
            Sc[a][1] = v0 + v1 + v2;   // interior
            Sc[a][2] = v1 + v2;        // col 251
        }
        #pragma unroll
        for (int cc = 0; cc < 3; cc++) {
            sWcat[0*3+cc] = Sc[0][cc] + Sc[1][cc];              // row 0
            sWcat[1*3+cc] = Sc[0][cc] + Sc[1][cc] + Sc[2][cc];  // interior
            sWcat[2*3+cc] = Sc[1][cc] + Sc[2][cc];              // row 251
        }
    }
    __syncthreads();

    const int cg   = tid & 63;      // 0..63, active < 63
    const int band = tid >> 6;      // 0..3
    float gsum = 0.f;

    if (cg < 63) {
        float w[49];
        #pragma unroll
        for (int k = 0; k < 49; k++) w[k] = sw[k];
        const float bias = sbias;

        const int q0 = cg * 4;
        // per-thread constant edge flags / clamped offsets
        const bool  okL = (q0 > 0);
        const bool  okR = (q0 + 8 < 256);
        const int   offL = okL ? (q0 - 1) : 0;
        const int   offR = okR ? (q0 + 8) : 255;

        float wv0[4], wv1[4], wv2[4];
        #pragma unroll
        for (int t = 0; t < 4; t++) {
            int q   = q0 + t;
            int cat = (q == 0) ? 0 : ((q == 251) ? 2 : 1);
            wv0[t] = sWcat[0*3 + cat];
            wv1[t] = sWcat[1*3 + cat];
            wv2[t] = sWcat[2*3 + cat];
        }

        const int lo = band * 63;                 // lo % 7 == 0
        const float* __restrict__ xm = x + (size_t)m * 65536;

        float acc[7][4];
        #pragma unroll
        for (int s = 0; s < 7; s++)
            #pragma unroll
            for (int t = 0; t < 4; t++) acc[s][t] = 0.f;

        for (int it = 0; it < 10; ++it) {
            #pragma unroll
            for (int u = 0; u < 7; u++) {
                const int  r    = lo - 1 + it * 7 + u;      // input row
                const bool rok  = ((unsigned)r < 256u);
                const int  rc   = rok ? r : (r < 0 ? 0 : 255);
                const float* __restrict__ row = xm + rc * 256;

                // unconditional loads from clamped addresses, FSEL zeroing
                float  xl = row[offL];
                float4 v0 = *reinterpret_cast<const float4*>(row + q0);
                float4 v1 = *reinterpret_cast<const float4*>(row + q0 + 4);
                float  xr = row[offR];

                float xw[10];
                xw[0] = (rok && okL) ? xl : 0.f;
                xw[1] = rok ? v0.x : 0.f;
                xw[2] = rok ? v0.y : 0.f;
                xw[3] = rok ? v0.z : 0.f;
                xw[4] = rok ? v0.w : 0.f;
                xw[5] = rok ? v1.x : 0.f;
                xw[6] = rok ? v1.y : 0.f;
                xw[7] = rok ? v1.z : 0.f;
                xw[8] = rok ? v1.w : 0.f;
                xw[9] = (rok && okR) ? xr : 0.f;

                // out row i = r+1-a -> slot (u - a) mod 7 (compile-time)
                #pragma unroll
                for (int a = 0; a < 7; a++) {
                    const int s = (u - a + 7) % 7;
                    #pragma unroll
                    for (int dx = 0; dx < 7; dx++) {
                        const float wk = w[a * 7 + dx];
                        acc[s][0] = fmaf(xw[0 + dx], wk, acc[s][0]);
                        acc[s][1] = fmaf(xw[1 + dx], wk, acc[s][1]);
                        acc[s][2] = fmaf(xw[2 + dx], wk, acc[s][2]);
                        acc[s][3] = fmaf(xw[3 + dx], wk, acc[s][3]);
                    }
                }

                // retire out row i = r-5, slot (u+1)%7 (compile-time), branch-free
                {
                    const int  off   = it * 7 + u - 6;       // i - lo
                    const int  sret  = (u + 1) % 7;
                    const bool offok = (off >= 0) && (off <= 62);
                    const int  i     = lo + off;
                    const bool top   = (i == 0), bot = (i == 251);
                    #pragma unroll
                    for (int t = 0; t < 4; t++) {
                        float h  = acc[sret][t] + bias;
                        float gl = 0.5f * h * (1.0f + erff(h * 0.7071067811865476f));
                        float ws = top ? wv0[t] : (bot ? wv2[t] : wv1[t]);
                        ws = offok ? ws : 0.f;
                        gsum = fmaf(gl, ws, gsum);
                        acc[sret][t] = 0.f;
                    }
                }
            }
        }
    }

    sred[tid] = gsum;
    __syncthreads();
    #pragma unroll
    for (int ofs = 128; ofs > 0; ofs >>= 1) {
        if (tid < ofs) sred[tid] += sred[tid + ofs];
        __syncthreads();
    }
    if (tid == 0) g_sums[m] = sred[0];
}

// =========================================================================
// Kernel B: per-batch MLP + sigmoid + gate + stable top-k via rank compute.
// 32 blocks (one per batch) x 64 threads.
// =========================================================================
__global__ __launch_bounds__(64)
void mlp_sort_kernel(const float* __restrict__ fc1w,
                     const float* __restrict__ fc1b,
                     const float* __restrict__ fc2w,
                     const float* __restrict__ fc2b,
                     float* __restrict__ out_idx)
{
    const int b   = blockIdx.x;
    const int tid = threadIdx.x;

    __shared__ float sg[25];
    __shared__ float shid[50];
    __shared__ float ss[25];

    if (tid < 25)
        sg[tid] = g_sums[b * 25 + tid] * (1.0f / 63504.0f);   // /252^2
    __syncthreads();

    if (tid < 50) {
        float v = fc1b[tid];
        #pragma unroll
        for (int c = 0; c < 25; c++) v = fmaf(sg[c], fc1w[tid * 25 + c], v);
        shid[tid] = v > 0.f ? v : 0.f;
    }
    __syncthreads();

    float sv = 0.f, gv = 0.f;
    if (tid < 25) {
        float z = fc2b[tid];
        #pragma unroll
        for (int j = 0; j < 50; j++) z = fmaf(shid[j], fc2w[tid * 50 + j], z);
        sv = 1.0f / (1.0f + expf(-z));
        float s2 = sv * sv;
        gv = s2 / (s2 + 1e-8f);
        ss[tid] = sv;
    }
    __syncthreads();

    if (tid < 25) {
        // rank in stable descending order: strictly-greater, or equal at lower idx
        int rank = 0;
        #pragma unroll
        for (int c = 0; c < 25; c++) {
            float o = ss[c];
            rank += (o > sv) || (o == sv && c < tid);
        }
        g_chan[b * 25 + rank]  = tid;
        g_gate[b * 25 + rank]  = gv;
        out_idx[b * 25 + rank] = (float)tid;
    }
}

// =========================================================================
// Kernel C: gated channel-permuted gather into (x_selected | x_plug)
// 16 float4 per thread in flight; evict-first streaming hints both ways.
// =========================================================================
__global__ __launch_bounds__(256)
void gather_kernel(const float* __restrict__ x, float* __restrict__ out)
{
    const int mp    = blockIdx.x;     // 0..3199
    const int map   = mp >> 2;        // (b,r)
    const int chunk = mp & 3;
    const int b = map / 25, r = map % 25;

    const int   ch = g_chan[map];
    const float gt = g_gate[map];

    const float4* __restrict__ src =
        reinterpret_cast<const float4*>(x + ((size_t)b * 25 + ch) * 65536);

    float* dbase;
    if (r < 10) dbase = out + ((size_t)b * 10 + r) * 65536;
    else        dbase = out + 20971520ull + ((size_t)b * 15 + (r - 10)) * 65536;
    float4* __restrict__ dst = reinterpret_cast<float4*>(dbase);

    const int base = chunk * 4096 + threadIdx.x;  // 16384 f4 per map, 4 chunks

    float4 v[16];
    #pragma unroll
    for (int k = 0; k < 16; k++) v[k] = __ldcs(&src[base + k * 256]);
    #pragma unroll
    for (int k = 0; k < 16; k++) {
        v[k].x *= gt; v[k].y *= gt; v[k].z *= gt; v[k].w *= gt;
        __stcs(&dst[base + k * 256], v[k]);
    }
}

// =========================================================================
extern "C" void kernel_launch(void* const* d_in, const int* in_sizes, int n_in,
                              void* d_out, int out_size)
{
    const float* x    = (const float*)d_in[0];
    const float* w7   = (const float*)d_in[1];
    const float* b7   = (const float*)d_in[2];
    const float* w3   = (const float*)d_in[3];
    const float* fc1w = (const float*)d_in[4];
    const float* fc1b = (const float*)d_in[5];
    const float* fc2w = (const float*)d_in[6];
    const float* fc2b = (const float*)d_in[7];
    float* out = (float*)d_out;

    conv_reduce_kernel<<<800, 256>>>(x, w7, b7, w3);
    mlp_sort_kernel<<<32, 64>>>(fc1w, fc1b, fc2w, fc2b, out + 52428800ull);
    gather_kernel<<<3200, 256>>>(x, out);
}

// round 6
// speedup vs baseline: 1.2857x; 1.0536x over previous
#include <cuda_runtime.h>
#include <math.h>

// ---------------- device scratch (no allocations allowed) ----------------
static __device__ float g_sums[32 * 25];
static __device__ float g_gate[32 * 25];
static __device__ int   g_chan[32 * 25];

// Fast exact-form GELU: 0.5*h*(1+erf(h/sqrt(2))) with Abramowitz-Stegun
// 7.1.26 erf (max abs err ~1.5e-7). ~11 fma-pipe ops + 2 MUFU.
__device__ __forceinline__ float fast_gelu(float h)
{
    const float az = fabsf(h) * 0.7071067811865476f;
    const float t  = __fdividef(1.0f, fmaf(0.3275911f, az, 1.0f));
    float p = fmaf(1.061405429f, t, -1.453152027f);
    p = fmaf(p, t, 1.421413741f);
    p = fmaf(p, t, -0.284496736f);
    p = fmaf(p, t, 0.254829592f);
    const float ex = __expf(-0.5f * h * h);          // exp(-az^2)
    float er = fmaf(-p * t, ex, 1.0f);               // erf(|z|)
    er = copysignf(er, h);
    return 0.5f * h * (1.0f + er);
}

// =========================================================================
// Kernel A: fused dwconv7 + bias + fast-exact GELU + region-weighted sum
// (dwconv3 + mean collapsed algebraically into 9 region weights)
// fp32 FFMA, branch-free inner loop (clamped rows + FSEL zeroing).
// One block per (b,c) map: 256 threads = 64 col-groups x 4 row bands,
// 4 output cols/thread, 7-deep ring accumulators, static slots.
// =========================================================================
__global__ __launch_bounds__(256, 2)
void conv_reduce_kernel(const float* __restrict__ x,
                        const float* __restrict__ w7,
                        const float* __restrict__ b7,
                        const float* __restrict__ w3)
{
    __shared__ float sw[49];
    __shared__ float sWcat[9];   // [rowcat*3 + colcat]
    __shared__ float sbias;
    __shared__ float sred[256];

    const int m = blockIdx.x;       // b*25 + c
    const int c = m % 25;
    const int tid = threadIdx.x;

    if (tid < 49) sw[tid] = w7[c * 49 + tid];
    if (tid == 49) sbias = b7[c];
    if (tid == 50) {
        const float* w3c = w3 + c * 9;
        float Sc[3][3];
        #pragma unroll
        for (int a = 0; a < 3; a++) {
            float v0 = w3c[a*3+0], v1 = w3c[a*3+1], v2 = w3c[a*3+2];
            Sc[a][0] = v0 + v1;        // col 0
            Sc[a][1] = v0 + v1 + v2;   // interior
            Sc[a][2] = v1 + v2;        // col 251
        }
        #pragma unroll
        for (int cc = 0; cc < 3; cc++) {
            sWcat[0*3+cc] = Sc[0][cc] + Sc[1][cc];              // row 0
            sWcat[1*3+cc] = Sc[0][cc] + Sc[1][cc] + Sc[2][cc];  // interior
            sWcat[2*3+cc] = Sc[1][cc] + Sc[2][cc];              // row 251
        }
    }
    __syncthreads();

    const int cg   = tid & 63;      // 0..63, active < 63
    const int band = tid >> 6;      // 0..3
    float gsum = 0.f;

    if (cg < 63) {
        float w[49];
        #pragma unroll
        for (int k = 0; k < 49; k++) w[k] = sw[k];
        const float bias = sbias;

        const int q0 = cg * 4;
        const bool  okL = (q0 > 0);
        const bool  okR = (q0 + 8 < 256);
        const int   offL = okL ? (q0 - 1) : 0;
        const int   offR = okR ? (q0 + 8) : 255;

        float wv0[4], wv1[4], wv2[4];
        #pragma unroll
        for (int t = 0; t < 4; t++) {
            int q   = q0 + t;
            int cat = (q == 0) ? 0 : ((q == 251) ? 2 : 1);
            wv0[t] = sWcat[0*3 + cat];
            wv1[t] = sWcat[1*3 + cat];
            wv2[t] = sWcat[2*3 + cat];
        }

        const int lo = band * 63;                 // lo % 7 == 0
        const float* __restrict__ xm = x + (size_t)m * 65536;

        float acc[7][4];
        #pragma unroll
        for (int s = 0; s < 7; s++)
            #pragma unroll
            for (int t = 0; t < 4; t++) acc[s][t] = 0.f;

        for (int it = 0; it < 10; ++it) {
            #pragma unroll
            for (int u = 0; u < 7; u++) {
                const int  r    = lo - 1 + it * 7 + u;      // input row
                const bool rok  = ((unsigned)r < 256u);
                const int  rc   = rok ? r : (r < 0 ? 0 : 255);
                const float* __restrict__ row = xm + rc * 256;

                // unconditional loads from clamped addresses, FSEL zeroing
                float  xl = row[offL];
                float4 v0 = *reinterpret_cast<const float4*>(row + q0);
                float4 v1 = *reinterpret_cast<const float4*>(row + q0 + 4);
                float  xr = row[offR];

                float xw[10];
                xw[0] = (rok && okL) ? xl : 0.f;
                xw[1] = rok ? v0.x : 0.f;
                xw[2] = rok ? v0.y : 0.f;
                xw[3] = rok ? v0.z : 0.f;
                xw[4] = rok ? v0.w : 0.f;
                xw[5] = rok ? v1.x : 0.f;
                xw[6] = rok ? v1.y : 0.f;
                xw[7] = rok ? v1.z : 0.f;
                xw[8] = rok ? v1.w : 0.f;
                xw[9] = (rok && okR) ? xr : 0.f;

                // out row i = r+1-a -> slot (u - a) mod 7 (compile-time)
                #pragma unroll
                for (int a = 0; a < 7; a++) {
                    const int s = (u - a + 7) % 7;
                    #pragma unroll
                    for (int dx = 0; dx < 7; dx++) {
                        const float wk = w[a * 7 + dx];
                        acc[s][0] = fmaf(xw[0 + dx], wk, acc[s][0]);
                        acc[s][1] = fmaf(xw[1 + dx], wk, acc[s][1]);
                        acc[s][2] = fmaf(xw[2 + dx], wk, acc[s][2]);
                        acc[s][3] = fmaf(xw[3 + dx], wk, acc[s][3]);
                    }
                }

                // retire out row i = r-5, slot (u+1)%7 (compile-time), branch-free
                {
                    const int  off   = it * 7 + u - 6;       // i - lo
                    const int  sret  = (u + 1) % 7;
                    const bool offok = (off >= 0) && (off <= 62);
                    const int  i     = lo + off;
                    const bool top   = (i == 0), bot = (i == 251);
                    #pragma unroll
                    for (int t = 0; t < 4; t++) {
                        float h  = acc[sret][t] + bias;
                        float gl = fast_gelu(h);
                        float ws = top ? wv0[t] : (bot ? wv2[t] : wv1[t]);
                        ws = offok ? ws : 0.f;
                        gsum = fmaf(gl, ws, gsum);
                        acc[sret][t] = 0.f;
                    }
                }
            }
        }
    }

    sred[tid] = gsum;
    __syncthreads();
    #pragma unroll
    for (int ofs = 128; ofs > 0; ofs >>= 1) {
        if (tid < ofs) sred[tid] += sred[tid + ofs];
        __syncthreads();
    }
    if (tid == 0) g_sums[m] = sred[0];
}

// =========================================================================
// Kernel B: per-batch MLP + sigmoid + gate + stable top-k via rank compute.
// 32 blocks (one per batch) x 64 threads.
// =========================================================================
__global__ __launch_bounds__(64)
void mlp_sort_kernel(const float* __restrict__ fc1w,
                     const float* __restrict__ fc1b,
                     const float* __restrict__ fc2w,
                     const float* __restrict__ fc2b,
                     float* __restrict__ out_idx)
{
    const int b   = blockIdx.x;
    const int tid = threadIdx.x;

    __shared__ float sg[25];
    __shared__ float shid[50];
    __shared__ float ss[25];

    if (tid < 25)
        sg[tid] = g_sums[b * 25 + tid] * (1.0f / 63504.0f);   // /252^2
    __syncthreads();

    if (tid < 50) {
        float v = fc1b[tid];
        #pragma unroll
        for (int c = 0; c < 25; c++) v = fmaf(sg[c], fc1w[tid * 25 + c], v);
        shid[tid] = v > 0.f ? v : 0.f;
    }
    __syncthreads();

    float sv = 0.f, gv = 0.f;
    if (tid < 25) {
        float z = fc2b[tid];
        #pragma unroll
        for (int j = 0; j < 50; j++) z = fmaf(shid[j], fc2w[tid * 50 + j], z);
        sv = 1.0f / (1.0f + expf(-z));
        float s2 = sv * sv;
        gv = s2 / (s2 + 1e-8f);
        ss[tid] = sv;
    }
    __syncthreads();

    if (tid < 25) {
        // rank in stable descending order: strictly-greater, or equal at lower idx
        int rank = 0;
        #pragma unroll
        for (int c = 0; c < 25; c++) {
            float o = ss[c];
            rank += (o > sv) || (o == sv && c < tid);
        }
        g_chan[b * 25 + rank]  = tid;
        g_gate[b * 25 + rank]  = gv;
        out_idx[b * 25 + rank] = (float)tid;
    }
}

// =========================================================================
// Kernel C: gated channel-permuted gather into (x_selected | x_plug)
// 16 float4 per thread in flight; evict-first streaming hints both ways.
// =========================================================================
__global__ __launch_bounds__(256)
void gather_kernel(const float* __restrict__ x, float* __restrict__ out)
{
    const int mp    = blockIdx.x;     // 0..3199
    const int map   = mp >> 2;        // (b,r)
    const int chunk = mp & 3;
    const int b = map / 25, r = map % 25;

    const int   ch = g_chan[map];
    const float gt = g_gate[map];

    const float4* __restrict__ src =
        reinterpret_cast<const float4*>(x + ((size_t)b * 25 + ch) * 65536);

    float* dbase;
    if (r < 10) dbase = out + ((size_t)b * 10 + r) * 65536;
    else        dbase = out + 20971520ull + ((size_t)b * 15 + (r - 10)) * 65536;
    float4* __restrict__ dst = reinterpret_cast<float4*>(dbase);

    const int base = chunk * 4096 + threadIdx.x;  // 16384 f4 per map, 4 chunks

    float4 v[16];
    #pragma unroll
    for (int k = 0; k < 16; k++) v[k] = __ldcs(&src[base + k * 256]);
    #pragma unroll
    for (int k = 0; k < 16; k++) {
        v[k].x *= gt; v[k].y *= gt; v[k].z *= gt; v[k].w *= gt;
        __stcs(&dst[base + k * 256], v[k]);
    }
}

// =========================================================================
extern "C" void kernel_launch(void* const* d_in, const int* in_sizes, int n_in,
                              void* d_out, int out_size)
{
    const float* x    = (const float*)d_in[0];
    const float* w7   = (const float*)d_in[1];
    const float* b7   = (const float*)d_in[2];
    const float* w3   = (const float*)d_in[3];
    const float* fc1w = (const float*)d_in[4];
    const float* fc1b = (const float*)d_in[5];
    const float* fc2w = (const float*)d_in[6];
    const float* fc2b = (const float*)d_in[7];
    float* out = (float*)d_out;

    conv_reduce_kernel<<<800, 256>>>(x, w7, b7, w3);
    mlp_sort_kernel<<<32, 64>>>(fc1w, fc1b, fc2w, fc2b, out + 52428800ull);
    gather_kernel<<<3200, 256>>>(x, out);
}

// round 7
// speedup vs baseline: 1.2977x; 1.0094x over previous
#include <cuda_runtime.h>
#include <math.h>

// ---------------- device scratch (no allocations allowed) ----------------
static __device__ float        g_sums[32 * 25];
static __device__ float        g_gate[32 * 25];
static __device__ int          g_chan[32 * 25];
static __device__ unsigned int g_done = 0;

// Fast exact-form GELU: 0.5*h*(1+erf(h/sqrt(2))) with Abramowitz-Stegun
// 7.1.26 erf (max abs err ~1.5e-7).
__device__ __forceinline__ float fast_gelu(float h)
{
    const float az = fabsf(h) * 0.7071067811865476f;
    const float t  = __fdividef(1.0f, fmaf(0.3275911f, az, 1.0f));
    float p = fmaf(1.061405429f, t, -1.453152027f);
    p = fmaf(p, t, 1.421413741f);
    p = fmaf(p, t, -0.284496736f);
    p = fmaf(p, t, 0.254829592f);
    const float ex = __expf(-0.5f * h * h);
    float er = fmaf(-p * t, ex, 1.0f);
    er = copysignf(er, h);
    return 0.5f * h * (1.0f + er);
}

// =========================================================================
// Kernel A: fused dwconv7 + bias + fast GELU + region-weighted spatial sum
// + (last block) MLP/sigmoid/gate/stable-top-k tail.
// Weights live in SHARED memory (volatile LDS in tap loop) to cap regs at
// <=85 -> 3 CTAs/SM (24 warps) for latency hiding; FFMA density unchanged.
// =========================================================================
__global__ __launch_bounds__(256, 3)
void conv_reduce_kernel(const float* __restrict__ x,
                        const float* __restrict__ w7,
                        const float* __restrict__ b7,
                        const float* __restrict__ w3,
                        const float* __restrict__ fc1w,
                        const float* __restrict__ fc1b,
                        const float* __restrict__ fc2w,
                        const float* __restrict__ fc2b,
                        float* __restrict__ out_idx)
{
    __shared__ float sw[49];
    __shared__ float sWcat[9];   // [rowcat*3 + colcat]
    __shared__ float sbias;
    __shared__ float sred[256];
    __shared__ bool  s_last;
    // tail MLP workspace
    __shared__ float sg[800];    // mean activations  [b][c]
    __shared__ float shid[1600]; // hidden layer      [b][j]
    __shared__ float ssv[800];   // sigmoid s         [b][c]
    __shared__ float sgv[800];   // gate value        [b][c]

    const int m = blockIdx.x;       // b*25 + c
    const int c = m % 25;
    const int tid = threadIdx.x;

    if (tid < 49) sw[tid] = w7[c * 49 + tid];
    if (tid == 49) sbias = b7[c];
    if (tid == 50) {
        const float* w3c = w3 + c * 9;
        float Sc[3][3];
        #pragma unroll
        for (int a = 0; a < 3; a++) {
            float v0 = w3c[a*3+0], v1 = w3c[a*3+1], v2 = w3c[a*3+2];
            Sc[a][0] = v0 + v1;        // col 0
            Sc[a][1] = v0 + v1 + v2;   // interior
            Sc[a][2] = v1 + v2;        // col 251
        }
        #pragma unroll
        for (int cc = 0; cc < 3; cc++) {
            sWcat[0*3+cc] = Sc[0][cc] + Sc[1][cc];              // row 0
            sWcat[1*3+cc] = Sc[0][cc] + Sc[1][cc] + Sc[2][cc];  // interior
            sWcat[2*3+cc] = Sc[1][cc] + Sc[2][cc];              // row 251
        }
    }
    __syncthreads();

    const int cg   = tid & 63;      // 0..63, active < 63
    const int band = tid >> 6;      // 0..3
    float gsum = 0.f;

    if (cg < 63) {
        volatile const float* vw = sw;   // volatile: weights stay in smem
        const float bias = sbias;

        const int q0 = cg * 4;
        const bool  okL = (q0 > 0);
        const bool  okR = (q0 + 8 < 256);
        const int   offL = okL ? (q0 - 1) : 0;
        const int   offR = okR ? (q0 + 8) : 255;

        float wv0[4], wv1[4], wv2[4];
        #pragma unroll
        for (int t = 0; t < 4; t++) {
            int q   = q0 + t;
            int cat = (q == 0) ? 0 : ((q == 251) ? 2 : 1);
            wv0[t] = sWcat[0*3 + cat];
            wv1[t] = sWcat[1*3 + cat];
            wv2[t] = sWcat[2*3 + cat];
        }

        const int lo = band * 63;                 // lo % 7 == 0
        const float* __restrict__ xm = x + (size_t)m * 65536;

        float acc[7][4];
        #pragma unroll
        for (int s = 0; s < 7; s++)
            #pragma unroll
            for (int t = 0; t < 4; t++) acc[s][t] = 0.f;

        for (int it = 0; it < 10; ++it) {
            #pragma unroll
            for (int u = 0; u < 7; u++) {
                const int  r    = lo - 1 + it * 7 + u;      // input row
                const bool rok  = ((unsigned)r < 256u);
                const int  rc   = rok ? r : (r < 0 ? 0 : 255);
                const float* __restrict__ row = xm + rc * 256;

                float  xl = row[offL];
                float4 v0 = *reinterpret_cast<const float4*>(row + q0);
                float4 v1 = *reinterpret_cast<const float4*>(row + q0 + 4);
                float  xr = row[offR];

                float xw[10];
                xw[0] = (rok && okL) ? xl : 0.f;
                xw[1] = rok ? v0.x : 0.f;
                xw[2] = rok ? v0.y : 0.f;
                xw[3] = rok ? v0.z : 0.f;
                xw[4] = rok ? v0.w : 0.f;
                xw[5] = rok ? v1.x : 0.f;
                xw[6] = rok ? v1.y : 0.f;
                xw[7] = rok ? v1.z : 0.f;
                xw[8] = rok ? v1.w : 0.f;
                xw[9] = (rok && okR) ? xr : 0.f;

                // out row i = r+1-a -> slot (u - a) mod 7 (compile-time)
                #pragma unroll
                for (int a = 0; a < 7; a++) {
                    const int s = (u - a + 7) % 7;
                    #pragma unroll
                    for (int dx = 0; dx < 7; dx++) {
                        const float wk = vw[a * 7 + dx];
                        acc[s][0] = fmaf(xw[0 + dx], wk, acc[s][0]);
                        acc[s][1] = fmaf(xw[1 + dx], wk, acc[s][1]);
                        acc[s][2] = fmaf(xw[2 + dx], wk, acc[s][2]);
                        acc[s][3] = fmaf(xw[3 + dx], wk, acc[s][3]);
                    }
                }

                // retire out row i = r-5, slot (u+1)%7, branch-free
                {
                    const int  off   = it * 7 + u - 6;       // i - lo
                    const int  sret  = (u + 1) % 7;
                    const bool offok = (off >= 0) && (off <= 62);
                    const int  i     = lo + off;
                    const bool top   = (i == 0), bot = (i == 251);
                    #pragma unroll
                    for (int t = 0; t < 4; t++) {
                        float h  = acc[sret][t] + bias;
                        float gl = fast_gelu(h);
                        float ws = top ? wv0[t] : (bot ? wv2[t] : wv1[t]);
                        ws = offok ? ws : 0.f;
                        gsum = fmaf(gl, ws, gsum);
                        acc[sret][t] = 0.f;
                    }
                }
            }
        }
    }

    sred[tid] = gsum;
    __syncthreads();
    #pragma unroll
    for (int ofs = 128; ofs > 0; ofs >>= 1) {
        if (tid < ofs) sred[tid] += sred[tid + ofs];
        __syncthreads();
    }
    if (tid == 0) g_sums[m] = sred[0];

    // ---------------- tail: last block runs the MLP + top-k ----------------
    if (tid == 0) {
        __threadfence();
        unsigned v = atomicAdd(&g_done, 1u);
        s_last = (v == gridDim.x - 1);
        if (s_last) g_done = 0;             // reset for next graph replay
    }
    __syncthreads();
    if (!s_last) return;

    // stage means
    for (int i = tid; i < 800; i += 256)
        sg[i] = g_sums[i] * (1.0f / 63504.0f);     // /252^2
    __syncthreads();

    // hidden layer: 32 batches x 50 units
    for (int i = tid; i < 1600; i += 256) {
        const int b = i / 50, j = i % 50;
        float v = fc1b[j];
        #pragma unroll
        for (int cc = 0; cc < 25; cc++)
            v = fmaf(sg[b * 25 + cc], fc1w[j * 25 + cc], v);
        shid[i] = v > 0.f ? v : 0.f;
    }
    __syncthreads();

    // output layer + sigmoid + gate
    for (int i = tid; i < 800; i += 256) {
        const int b = i / 25, cc = i % 25;
        float z = fc2b[cc];
        #pragma unroll
        for (int j = 0; j < 50; j++)
            z = fmaf(shid[b * 50 + j], fc2w[cc * 50 + j], z);
        float s  = 1.0f / (1.0f + expf(-z));
        ssv[i] = s;
        float s2 = s * s;
        sgv[i] = s2 / (s2 + 1e-8f);
    }
    __syncthreads();

    // stable descending rank (matches jax.lax.top_k tie-breaking)
    for (int i = tid; i < 800; i += 256) {
        const int b = i / 25, cc = i % 25;
        const float sv = ssv[i];
        int rank = 0;
        #pragma unroll
        for (int o = 0; o < 25; o++) {
            float ov = ssv[b * 25 + o];
            rank += (ov > sv) || (ov == sv && o < cc);
        }
        g_chan[b * 25 + rank]  = cc;
        g_gate[b * 25 + rank]  = sgv[i];
        out_idx[b * 25 + rank] = (float)cc;
    }
}

// =========================================================================
// Kernel C: gated channel-permuted gather into (x_selected | x_plug)
// 16 float4 per thread in flight; evict-first streaming hints both ways.
// =========================================================================
__global__ __launch_bounds__(256)
void gather_kernel(const float* __restrict__ x, float* __restrict__ out)
{
    const int mp    = blockIdx.x;     // 0..3199
    const int map   = mp >> 2;        // (b,r)
    const int chunk = mp & 3;
    const int b = map / 25, r = map % 25;

    const int   ch = g_chan[map];
    const float gt = g_gate[map];

    const float4* __restrict__ src =
        reinterpret_cast<const float4*>(x + ((size_t)b * 25 + ch) * 65536);

    float* dbase;
    if (r < 10) dbase = out + ((size_t)b * 10 + r) * 65536;
    else        dbase = out + 20971520ull + ((size_t)b * 15 + (r - 10)) * 65536;
    float4* __restrict__ dst = reinterpret_cast<float4*>(dbase);

    const int base = chunk * 4096 + threadIdx.x;  // 16384 f4 per map, 4 chunks

    float4 v[16];
    #pragma unroll
    for (int k = 0; k < 16; k++) v[k] = __ldcs(&src[base + k * 256]);
    #pragma unroll
    for (int k = 0; k < 16; k++) {
        v[k].x *= gt; v[k].y *= gt; v[k].z *= gt; v[k].w *= gt;
        __stcs(&dst[base + k * 256], v[k]);
    }
}

// =========================================================================
extern "C" void kernel_launch(void* const* d_in, const int* in_sizes, int n_in,
                              void* d_out, int out_size)
{
    const float* x    = (const float*)d_in[0];
    const float* w7   = (const float*)d_in[1];
    const float* b7   = (const float*)d_in[2];
    const float* w3   = (const float*)d_in[3];
    const float* fc1w = (const float*)d_in[4];
    const float* fc1b = (const float*)d_in[5];
    const float* fc2w = (const float*)d_in[6];
    const float* fc2b = (const float*)d_in[7];
    float* out = (float*)d_out;

    conv_reduce_kernel<<<800, 256>>>(x, w7, b7, w3,
                                     fc1w, fc1b, fc2w, fc2b,
                                     out + 52428800ull);
    gather_kernel<<<3200, 256>>>(x, out);
}

// round 8
// speedup vs baseline: 1.3327x; 1.0270x over previous
#include <cuda_runtime.h>
#include <math.h>

// ---------------- device scratch (no allocations allowed) ----------------
static __device__ float        g_sums[32 * 25];
static __device__ float        g_gate[32 * 25];
static __device__ int          g_chan[32 * 25];
static __device__ unsigned int g_done = 0;

// Fast exact-form GELU: 0.5*h*(1+erf(h/sqrt(2))) with Abramowitz-Stegun
// 7.1.26 erf (max abs err ~1.5e-7).
__device__ __forceinline__ float fast_gelu(float h)
{
    const float az = fabsf(h) * 0.7071067811865476f;
    const float t  = __fdividef(1.0f, fmaf(0.3275911f, az, 1.0f));
    float p = fmaf(1.061405429f, t, -1.453152027f);
    p = fmaf(p, t, 1.421413741f);
    p = fmaf(p, t, -0.284496736f);
    p = fmaf(p, t, 0.254829592f);
    const float ex = __expf(-0.5f * h * h);
    float er = fmaf(-p * t, ex, 1.0f);
    er = copysignf(er, h);
    return 0.5f * h * (1.0f + er);
}

// =========================================================================
// Kernel A: fused dwconv7 + bias + fast GELU + region-weighted spatial sum
// + (last block) MLP/sigmoid/gate/stable-top-k tail.
// Software-pipelined rows: loads for row r+1 issue before the 196-FMA block
// of row r; FSEL zeroing doubles as the buffer commit (no MOV copies).
// Edge region-weights via rare warp-uniform branch (frees 8 regs).
// =========================================================================
__global__ __launch_bounds__(256, 2)
void conv_reduce_kernel(const float* __restrict__ x,
                        const float* __restrict__ w7,
                        const float* __restrict__ b7,
                        const float* __restrict__ w3,
                        const float* __restrict__ fc1w,
                        const float* __restrict__ fc1b,
                        const float* __restrict__ fc2w,
                        const float* __restrict__ fc2b,
                        float* __restrict__ out_idx)
{
    __shared__ float sw[49];
    __shared__ float sWcat[9];   // [rowcat*3 + colcat]
    __shared__ float sbias;
    __shared__ float sred[256];
    __shared__ bool  s_last;
    // tail MLP workspace
    __shared__ float sg[800];
    __shared__ float shid[1600];
    __shared__ float ssv[800];
    __shared__ float sgv[800];

    const int m = blockIdx.x;       // b*25 + c
    const int c = m % 25;
    const int tid = threadIdx.x;

    if (tid < 49) sw[tid] = w7[c * 49 + tid];
    if (tid == 49) sbias = b7[c];
    if (tid == 50) {
        const float* w3c = w3 + c * 9;
        float Sc[3][3];
        #pragma unroll
        for (int a = 0; a < 3; a++) {
            float v0 = w3c[a*3+0], v1 = w3c[a*3+1], v2 = w3c[a*3+2];
            Sc[a][0] = v0 + v1;        // col 0
            Sc[a][1] = v0 + v1 + v2;   // interior
            Sc[a][2] = v1 + v2;        // col 251
        }
        #pragma unroll
        for (int cc = 0; cc < 3; cc++) {
            sWcat[0*3+cc] = Sc[0][cc] + Sc[1][cc];              // row 0
            sWcat[1*3+cc] = Sc[0][cc] + Sc[1][cc] + Sc[2][cc];  // interior
            sWcat[2*3+cc] = Sc[1][cc] + Sc[2][cc];              // row 251
        }
    }
    __syncthreads();

    const int cg   = tid & 63;      // 0..63, active < 63
    const int band = tid >> 6;      // 0..3
    float gsum = 0.f;

    if (cg < 63) {
        float w[49];
        #pragma unroll
        for (int k = 0; k < 49; k++) w[k] = sw[k];
        const float bias = sbias;

        const int q0 = cg * 4;
        const bool  okL = (q0 > 0);
        const bool  okR = (q0 + 8 < 256);
        const int   offL = okL ? (q0 - 1) : 0;
        const int   offR = okR ? (q0 + 8) : 255;

        // interior-row region weights per output column (rowcat = 1)
        float wv1[4];
        #pragma unroll
        for (int t = 0; t < 4; t++) {
            int q   = q0 + t;
            int cat = (q == 0) ? 0 : ((q == 251) ? 2 : 1);
            wv1[t] = sWcat[1*3 + cat];
        }

        const int lo = band * 63;                 // lo % 7 == 0
        const float* __restrict__ xm = x + (size_t)m * 65536;

        float buf[10];
        // ---- prologue: row lo-1 into buf ----
        {
            const int  r   = lo - 1;
            const bool rok = (r >= 0);
            const float* __restrict__ row = xm + (rok ? r : 0) * 256;
            float  xl = row[offL];
            float4 v0 = *reinterpret_cast<const float4*>(row + q0);
            float4 v1 = *reinterpret_cast<const float4*>(row + q0 + 4);
            float  xr = row[offR];
            buf[0] = (rok && okL) ? xl : 0.f;
            buf[1] = rok ? v0.x : 0.f;  buf[2] = rok ? v0.y : 0.f;
            buf[3] = rok ? v0.z : 0.f;  buf[4] = rok ? v0.w : 0.f;
            buf[5] = rok ? v1.x : 0.f;  buf[6] = rok ? v1.y : 0.f;
            buf[7] = rok ? v1.z : 0.f;  buf[8] = rok ? v1.w : 0.f;
            buf[9] = (rok && okR) ? xr : 0.f;
        }

        float acc[7][4];
        #pragma unroll
        for (int s = 0; s < 7; s++)
            #pragma unroll
            for (int t = 0; t < 4; t++) acc[s][t] = 0.f;

        for (int it = 0; it < 10; ++it) {
            #pragma unroll
            for (int u = 0; u < 7; u++) {
                const int r = lo - 1 + it * 7 + u;   // row currently in buf

                // ---- issue next-row loads (hide under FMA block below) ----
                const int  rn   = r + 1;
                const bool rokn = ((unsigned)rn < 256u);
                const int  rcn  = rokn ? rn : 255;   // rn >= 0 always
                const float* __restrict__ rowp = xm + rcn * 256;
                float  nxl = rowp[offL];
                float4 nv0 = *reinterpret_cast<const float4*>(rowp + q0);
                float4 nv1 = *reinterpret_cast<const float4*>(rowp + q0 + 4);
                float  nxr = rowp[offR];

                // ---- 196 FMAs on buf (row r) ----
                // out row i = r+1-a -> slot (u - a) mod 7 (compile-time)
                #pragma unroll
                for (int a = 0; a < 7; a++) {
                    const int s = (u - a + 7) % 7;
                    #pragma unroll
                    for (int dx = 0; dx < 7; dx++) {
                        const float wk = w[a * 7 + dx];
                        acc[s][0] = fmaf(buf[dx],     wk, acc[s][0]);
                        acc[s][1] = fmaf(buf[dx + 1], wk, acc[s][1]);
                        acc[s][2] = fmaf(buf[dx + 2], wk, acc[s][2]);
                        acc[s][3] = fmaf(buf[dx + 3], wk, acc[s][3]);
                    }
                }

                // ---- retire out row i = r-5, slot (u+1)%7 ----
                {
                    const int  off   = it * 7 + u - 6;       // i - lo
                    const int  sret  = (u + 1) % 7;
                    const bool offok = (off >= 0) && (off <= 62);
                    const int  i     = lo + off;
                    const bool edge  = (i == 0) || (i == 251);  // warp-uniform, rare

                    float wsv[4];
                    #pragma unroll
                    for (int t = 0; t < 4; t++) wsv[t] = wv1[t];
                    if (edge) {
                        const int rowcat = (i == 0) ? 0 : 2;
                        #pragma unroll
                        for (int t = 0; t < 4; t++) {
                            const int q = q0 + t;
                            const int colcat = (q == 0) ? 0 : ((q == 251) ? 2 : 1);
                            wsv[t] = sWcat[rowcat * 3 + colcat];
                        }
                    }
                    #pragma unroll
                    for (int t = 0; t < 4; t++) {
                        float h  = acc[sret][t] + bias;
                        float gl = fast_gelu(h);
                        float ws = offok ? wsv[t] : 0.f;
                        gsum = fmaf(gl, ws, gsum);
                        acc[sret][t] = 0.f;
                    }
                }

                // ---- commit prefetch: FSEL raw -> buf (row r+1) ----
                buf[0] = (rokn && okL) ? nxl : 0.f;
                buf[1] = rokn ? nv0.x : 0.f;  buf[2] = rokn ? nv0.y : 0.f;
                buf[3] = rokn ? nv0.z : 0.f;  buf[4] = rokn ? nv0.w : 0.f;
                buf[5] = rokn ? nv1.x : 0.f;  buf[6] = rokn ? nv1.y : 0.f;
                buf[7] = rokn ? nv1.z : 0.f;  buf[8] = rokn ? nv1.w : 0.f;
                buf[9] = (rokn && okR) ? nxr : 0.f;
            }
        }
    }

    sred[tid] = gsum;
    __syncthreads();
    #pragma unroll
    for (int ofs = 128; ofs > 0; ofs >>= 1) {
        if (tid < ofs) sred[tid] += sred[tid + ofs];
        __syncthreads();
    }
    if (tid == 0) g_sums[m] = sred[0];

    // ---------------- tail: last block runs the MLP + top-k ----------------
    if (tid == 0) {
        __threadfence();
        unsigned v = atomicAdd(&g_done, 1u);
        s_last = (v == gridDim.x - 1);
        if (s_last) g_done = 0;             // reset for next graph replay
    }
    __syncthreads();
    if (!s_last) return;

    for (int i = tid; i < 800; i += 256)
        sg[i] = g_sums[i] * (1.0f / 63504.0f);     // /252^2
    __syncthreads();

    for (int i = tid; i < 1600; i += 256) {
        const int b = i / 50, j = i % 50;
        float v = fc1b[j];
        #pragma unroll
        for (int cc = 0; cc < 25; cc++)
            v = fmaf(sg[b * 25 + cc], fc1w[j * 25 + cc], v);
        shid[i] = v > 0.f ? v : 0.f;
    }
    __syncthreads();

    for (int i = tid; i < 800; i += 256) {
        const int b = i / 25, cc = i % 25;
        float z = fc2b[cc];
        #pragma unroll
        for (int j = 0; j < 50; j++)
            z = fmaf(shid[b * 50 + j], fc2w[cc * 50 + j], z);
        float s  = 1.0f / (1.0f + expf(-z));
        ssv[i] = s;
        float s2 = s * s;
        sgv[i] = s2 / (s2 + 1e-8f);
    }
    __syncthreads();

    for (int i = tid; i < 800; i += 256) {
        const int b = i / 25, cc = i % 25;
        const float sv = ssv[i];
        int rank = 0;
        #pragma unroll
        for (int o = 0; o < 25; o++) {
            float ov = ssv[b * 25 + o];
            rank += (ov > sv) || (ov == sv && o < cc);
        }
        g_chan[b * 25 + rank]  = cc;
        g_gate[b * 25 + rank]  = sgv[i];
        out_idx[b * 25 + rank] = (float)cc;
    }
}

// =========================================================================
// Kernel C: gated channel-permuted gather into (x_selected | x_plug)
// 16 float4 per thread in flight; evict-first streaming hints both ways.
// =========================================================================
__global__ __launch_bounds__(256)
void gather_kernel(const float* __restrict__ x, float* __restrict__ out)
{
    const int mp    = blockIdx.x;     // 0..3199
    const int map   = mp >> 2;        // (b,r)
    const int chunk = mp & 3;
    const int b = map / 25, r = map % 25;

    const int   ch = g_chan[map];
    const float gt = g_gate[map];

    const float4* __restrict__ src =
        reinterpret_cast<const float4*>(x + ((size_t)b * 25 + ch) * 65536);

    float* dbase;
    if (r < 10) dbase = out + ((size_t)b * 10 + r) * 65536;
    else        dbase = out + 20971520ull + ((size_t)b * 15 + (r - 10)) * 65536;
    float4* __restrict__ dst = reinterpret_cast<float4*>(dbase);

    const int base = chunk * 4096 + threadIdx.x;  // 16384 f4 per map, 4 chunks

    float4 v[16];
    #pragma unroll
    for (int k = 0; k < 16; k++) v[k] = __ldcs(&src[base + k * 256]);
    #pragma unroll
    for (int k = 0; k < 16; k++) {
        v[k].x *= gt; v[k].y *= gt; v[k].z *= gt; v[k].w *= gt;
        __stcs(&dst[base + k * 256], v[k]);
    }
}

// =========================================================================
extern "C" void kernel_launch(void* const* d_in, const int* in_sizes, int n_in,
                              void* d_out, int out_size)
{
    const float* x    = (const float*)d_in[0];
    const float* w7   = (const float*)d_in[1];
    const float* b7   = (const float*)d_in[2];
    const float* w3   = (const float*)d_in[3];
    const float* fc1w = (const float*)d_in[4];
    const float* fc1b = (const float*)d_in[5];
    const float* fc2w = (const float*)d_in[6];
    const float* fc2b = (const float*)d_in[7];
    float* out = (float*)d_out;

    conv_reduce_kernel<<<800, 256>>>(x, w7, b7, w3,
                                     fc1w, fc1b, fc2w, fc2b,
                                     out + 52428800ull);
    gather_kernel<<<3200, 256>>>(x, out);
}

// round 9
// speedup vs baseline: 1.3371x; 1.0033x over previous
#include <cuda_runtime.h>
#include <math.h>

// ---------------- device scratch (no allocations allowed) ----------------
static __device__ float        g_sums[32 * 25];
static __device__ float        g_gate[32 * 25];
static __device__ int          g_chan[32 * 25];
static __device__ unsigned int g_done = 0;

// Fast exact-form GELU: 0.5*h*(1+erf(h/sqrt(2))) with Abramowitz-Stegun
// 7.1.26 erf (max abs err ~1.5e-7).
__device__ __forceinline__ float fast_gelu(float h)
{
    const float az = fabsf(h) * 0.7071067811865476f;
    const float t  = __fdividef(1.0f, fmaf(0.3275911f, az, 1.0f));
    float p = fmaf(1.061405429f, t, -1.453152027f);
    p = fmaf(p, t, 1.421413741f);
    p = fmaf(p, t, -0.284496736f);
    p = fmaf(p, t, 0.254829592f);
    const float ex = __expf(-0.5f * h * h);
    float er = fmaf(-p * t, ex, 1.0f);
    er = copysignf(er, h);
    return 0.5f * h * (1.0f + er);
}

// =========================================================================
// Kernel A: fused dwconv7 + bias + fast GELU + region-weighted spatial sum
// + (last block) MLP/sigmoid/gate/stable-top-k tail.
// Software-pipelined rows: loads for row r+1 issue before the 196-FMA block
// of row r; FSEL zeroing doubles as the buffer commit (no MOV copies).
// Edge region-weights via rare warp-uniform branch (frees 8 regs).
// =========================================================================
__global__ __launch_bounds__(256, 2)
void conv_reduce_kernel(const float* __restrict__ x,
                        const float* __restrict__ w7,
                        const float* __restrict__ b7,
                        const float* __restrict__ w3,
                        const float* __restrict__ fc1w,
                        const float* __restrict__ fc1b,
                        const float* __restrict__ fc2w,
                        const float* __restrict__ fc2b,
                        float* __restrict__ out_idx)
{
    __shared__ float sw[49];
    __shared__ float sWcat[9];   // [rowcat*3 + colcat]
    __shared__ float sbias;
    __shared__ float sred[256];
    __shared__ bool  s_last;
    // tail MLP workspace
    __shared__ float sg[800];
    __shared__ float shid[1600];
    __shared__ float ssv[800];
    __shared__ float sgv[800];

    const int m = blockIdx.x;       // b*25 + c
    const int c = m % 25;
    const int tid = threadIdx.x;

    if (tid < 49) sw[tid] = w7[c * 49 + tid];
    if (tid == 49) sbias = b7[c];
    if (tid == 50) {
        const float* w3c = w3 + c * 9;
        float Sc[3][3];
        #pragma unroll
        for (int a = 0; a < 3; a++) {
            float v0 = w3c[a*3+0], v1 = w3c[a*3+1], v2 = w3c[a*3+2];
            Sc[a][0] = v0 + v1;        // col 0
            Sc[a][1] = v0 + v1 + v2;   // interior
            Sc[a][2] = v1 + v2;        // col 251
        }
        #pragma unroll
        for (int cc = 0; cc < 3; cc++) {
            sWcat[0*3+cc] = Sc[0][cc] + Sc[1][cc];              // row 0
            sWcat[1*3+cc] = Sc[0][cc] + Sc[1][cc] + Sc[2][cc];  // interior
            sWcat[2*3+cc] = Sc[1][cc] + Sc[2][cc];              // row 251
        }
    }
    __syncthreads();

    const int cg   = tid & 63;      // 0..63, active < 63
    const int band = tid >> 6;      // 0..3
    float gsum = 0.f;

    if (cg < 63) {
        float w[49];
        #pragma unroll
        for (int k = 0; k < 49; k++) w[k] = sw[k];
        const float bias = sbias;

        const int q0 = cg * 4;
        const bool  okL = (q0 > 0);
        const bool  okR = (q0 + 8 < 256);
        const int   offL = okL ? (q0 - 1) : 0;
        const int   offR = okR ? (q0 + 8) : 255;

        // interior-row region weights per output column (rowcat = 1)
        float wv1[4];
        #pragma unroll
        for (int t = 0; t < 4; t++) {
            int q   = q0 + t;
            int cat = (q == 0) ? 0 : ((q == 251) ? 2 : 1);
            wv1[t] = sWcat[1*3 + cat];
        }

        const int lo = band * 63;                 // lo % 7 == 0
        const float* __restrict__ xm = x + (size_t)m * 65536;

        float buf[10];
        // ---- prologue: row lo-1 into buf ----
        {
            const int  r   = lo - 1;
            const bool rok = (r >= 0);
            const float* __restrict__ row = xm + (rok ? r : 0) * 256;
            float  xl = row[offL];
            float4 v0 = *reinterpret_cast<const float4*>(row + q0);
            float4 v1 = *reinterpret_cast<const float4*>(row + q0 + 4);
            float  xr = row[offR];
            buf[0] = (rok && okL) ? xl : 0.f;
            buf[1] = rok ? v0.x : 0.f;  buf[2] = rok ? v0.y : 0.f;
            buf[3] = rok ? v0.z : 0.f;  buf[4] = rok ? v0.w : 0.f;
            buf[5] = rok ? v1.x : 0.f;  buf[6] = rok ? v1.y : 0.f;
            buf[7] = rok ? v1.z : 0.f;  buf[8] = rok ? v1.w : 0.f;
            buf[9] = (rok && okR) ? xr : 0.f;
        }

        float acc[7][4];
        #pragma unroll
        for (int s = 0; s < 7; s++)
            #pragma unroll
            for (int t = 0; t < 4; t++) acc[s][t] = 0.f;

        for (int it = 0; it < 10; ++it) {
            #pragma unroll
            for (int u = 0; u < 7; u++) {
                const int r = lo - 1 + it * 7 + u;   // row currently in buf

                // ---- issue next-row loads (hide under FMA block below) ----
                const int  rn   = r + 1;
                const bool rokn = ((unsigned)rn < 256u);
                const int  rcn  = rokn ? rn : 255;   // rn >= 0 always
                const float* __restrict__ rowp = xm + rcn * 256;
                float  nxl = rowp[offL];
                float4 nv0 = *reinterpret_cast<const float4*>(rowp + q0);
                float4 nv1 = *reinterpret_cast<const float4*>(rowp + q0 + 4);
                float  nxr = rowp[offR];

                // ---- 196 FMAs on buf (row r) ----
                // out row i = r+1-a -> slot (u - a) mod 7 (compile-time)
                #pragma unroll
                for (int a = 0; a < 7; a++) {
                    const int s = (u - a + 7) % 7;
                    #pragma unroll
                    for (int dx = 0; dx < 7; dx++) {
                        const float wk = w[a * 7 + dx];
                        acc[s][0] = fmaf(buf[dx],     wk, acc[s][0]);
                        acc[s][1] = fmaf(buf[dx + 1], wk, acc[s][1]);
                        acc[s][2] = fmaf(buf[dx + 2], wk, acc[s][2]);
                        acc[s][3] = fmaf(buf[dx + 3], wk, acc[s][3]);
                    }
                }

                // ---- retire out row i = r-5, slot (u+1)%7 ----
                {
                    const int  off   = it * 7 + u - 6;       // i - lo
                    const int  sret  = (u + 1) % 7;
                    const bool offok = (off >= 0) && (off <= 62);
                    const int  i     = lo + off;
                    const bool edge  = (i == 0) || (i == 251);  // warp-uniform, rare

                    float wsv[4];
                    #pragma unroll
                    for (int t = 0; t < 4; t++) wsv[t] = wv1[t];
                    if (edge) {
                        const int rowcat = (i == 0) ? 0 : 2;
                        #pragma unroll
                        for (int t = 0; t < 4; t++) {
                            const int q = q0 + t;
                            const int colcat = (q == 0) ? 0 : ((q == 251) ? 2 : 1);
                            wsv[t] = sWcat[rowcat * 3 + colcat];
                        }
                    }
                    #pragma unroll
                    for (int t = 0; t < 4; t++) {
                        float h  = acc[sret][t] + bias;
                        float gl = fast_gelu(h);
                        float ws = offok ? wsv[t] : 0.f;
                        gsum = fmaf(gl, ws, gsum);
                        acc[sret][t] = 0.f;
                    }
                }

                // ---- commit prefetch: FSEL raw -> buf (row r+1) ----
                buf[0] = (rokn && okL) ? nxl : 0.f;
                buf[1] = rokn ? nv0.x : 0.f;  buf[2] = rokn ? nv0.y : 0.f;
                buf[3] = rokn ? nv0.z : 0.f;  buf[4] = rokn ? nv0.w : 0.f;
                buf[5] = rokn ? nv1.x : 0.f;  buf[6] = rokn ? nv1.y : 0.f;
                buf[7] = rokn ? nv1.z : 0.f;  buf[8] = rokn ? nv1.w : 0.f;
                buf[9] = (rokn && okR) ? nxr : 0.f;
            }
        }
    }

    sred[tid] = gsum;
    __syncthreads();
    #pragma unroll
    for (int ofs = 128; ofs > 0; ofs >>= 1) {
        if (tid < ofs) sred[tid] += sred[tid + ofs];
        __syncthreads();
    }
    if (tid == 0) g_sums[m] = sred[0];

    // ---------------- tail: last block runs the MLP + top-k ----------------
    if (tid == 0) {
        __threadfence();
        unsigned v = atomicAdd(&g_done, 1u);
        s_last = (v == gridDim.x - 1);
        if (s_last) g_done = 0;             // reset for next graph replay
    }
    __syncthreads();
    if (!s_last) return;

    for (int i = tid; i < 800; i += 256)
        sg[i] = g_sums[i] * (1.0f / 63504.0f);     // /252^2
    __syncthreads();

    for (int i = tid; i < 1600; i += 256) {
        const int b = i / 50, j = i % 50;
        float v = fc1b[j];
        #pragma unroll
        for (int cc = 0; cc < 25; cc++)
            v = fmaf(sg[b * 25 + cc], fc1w[j * 25 + cc], v);
        shid[i] = v > 0.f ? v : 0.f;
    }
    __syncthreads();

    for (int i = tid; i < 800; i += 256) {
        const int b = i / 25, cc = i % 25;
        float z = fc2b[cc];
        #pragma unroll
        for (int j = 0; j < 50; j++)
            z = fmaf(shid[b * 50 + j], fc2w[cc * 50 + j], z);
        float s  = 1.0f / (1.0f + expf(-z));
        ssv[i] = s;
        float s2 = s * s;
        sgv[i] = s2 / (s2 + 1e-8f);
    }
    __syncthreads();

    for (int i = tid; i < 800; i += 256) {
        const int b = i / 25, cc = i % 25;
        const float sv = ssv[i];
        int rank = 0;
        #pragma unroll
        for (int o = 0; o < 25; o++) {
            float ov = ssv[b * 25 + o];
            rank += (ov > sv) || (ov == sv && o < cc);
        }
        g_chan[b * 25 + rank]  = cc;
        g_gate[b * 25 + rank]  = sgv[i];
        out_idx[b * 25 + rank] = (float)cc;
    }
}

// =========================================================================
// Kernel C: gated channel-permuted gather into (x_selected | x_plug)
// 16 float4 per thread in flight; evict-first streaming hints both ways.
// =========================================================================
__global__ __launch_bounds__(256)
void gather_kernel(const float* __restrict__ x, float* __restrict__ out)
{
    const int mp    = blockIdx.x;     // 0..3199
    const int map   = mp >> 2;        // (b,r)
    const int chunk = mp & 3;
    const int b = map / 25, r = map % 25;

    const int   ch = g_chan[map];
    const float gt = g_gate[map];

    const float4* __restrict__ src =
        reinterpret_cast<const float4*>(x + ((size_t)b * 25 + ch) * 65536);

    float* dbase;
    if (r < 10) dbase = out + ((size_t)b * 10 + r) * 65536;
    else        dbase = out + 20971520ull + ((size_t)b * 15 + (r - 10)) * 65536;
    float4* __restrict__ dst = reinterpret_cast<float4*>(dbase);

    const int base = chunk * 4096 + threadIdx.x;  // 16384 f4 per map, 4 chunks

    float4 v[16];
    #pragma unroll
    for (int k = 0; k < 16; k++) v[k] = __ldcs(&src[base + k * 256]);
    #pragma unroll
    for (int k = 0; k < 16; k++) {
        v[k].x *= gt; v[k].y *= gt; v[k].z *= gt; v[k].w *= gt;
        __stcs(&dst[base + k * 256], v[k]);
    }
}

// =========================================================================
extern "C" void kernel_launch(void* const* d_in, const int* in_sizes, int n_in,
                              void* d_out, int out_size)
{
    const float* x    = (const float*)d_in[0];
    const float* w7   = (const float*)d_in[1];
    const float* b7   = (const float*)d_in[2];
    const float* w3   = (const float*)d_in[3];
    const float* fc1w = (const float*)d_in[4];
    const float* fc1b = (const float*)d_in[5];
    const float* fc2w = (const float*)d_in[6];
    const float* fc2b = (const float*)d_in[7];
    float* out = (float*)d_out;

    conv_reduce_kernel<<<800, 256>>>(x, w7, b7, w3,
                                     fc1w, fc1b, fc2w, fc2b,
                                     out + 52428800ull);
    gather_kernel<<<3200, 256>>>(x, out);
}

// round 10
// speedup vs baseline: 1.5681x; 1.1727x over previous
#include <cuda_runtime.h>
#include <math.h>

// ---------------- device scratch (no allocations allowed) ----------------
static __device__ float         g_sums[32 * 25];
static __device__ float         g_gate[32 * 25];
static __device__ int           g_chan[32 * 25];
static __device__ unsigned int  g_conv_ctr   = 0;
static __device__ unsigned int  g_gather_ctr = 0;
static __device__ unsigned int  g_exit_ctr   = 0;
static __device__ unsigned int  g_batch_cnt[32];
static __device__ volatile int  g_batch_ready[32];

// Fast exact-form GELU: 0.5*h*(1+erf(h/sqrt(2))) with Abramowitz-Stegun
// 7.1.26 erf (max abs err ~1.5e-7).
__device__ __forceinline__ float fast_gelu(float h)
{
    const float az = fabsf(h) * 0.7071067811865476f;
    const float t  = __fdividef(1.0f, fmaf(0.3275911f, az, 1.0f));
    float p = fmaf(1.061405429f, t, -1.453152027f);
    p = fmaf(p, t, 1.421413741f);
    p = fmaf(p, t, -0.284496736f);
    p = fmaf(p, t, 0.254829592f);
    const float ex = __expf(-0.5f * h * h);
    float er = fmaf(-p * t, ex, 1.0f);
    er = copysignf(er, h);
    return 0.5f * h * (1.0f + er);
}

// =========================================================================
// Persistent mega-kernel: dynamic conv queue (800 map units) -> inline
// per-batch MLP/top-k when a batch's 25 maps complete -> gather queue
// (3200 chunks, gated on per-batch ready flags). Conv is fma-bound, gather
// is DRAM-bound; the overlap hides gather traffic under conv compute.
// =========================================================================
__global__ __launch_bounds__(256, 2)
void mega_kernel(const float* __restrict__ x,
                 const float* __restrict__ w7,
                 const float* __restrict__ b7,
                 const float* __restrict__ w3,
                 const float* __restrict__ fc1w,
                 const float* __restrict__ fc1b,
                 const float* __restrict__ fc2w,
                 const float* __restrict__ fc2b,
                 float* __restrict__ out)
{
    __shared__ float sw[49];
    __shared__ float sWcat[9];
    __shared__ float sbias;
    __shared__ float sred[256];
    __shared__ int   s_unit;
    __shared__ int   s_mlpb;
    __shared__ float bs_g[25];
    __shared__ float bs_hid[50];
    __shared__ float bs_s[25];

    const int tid = threadIdx.x;
    float* __restrict__ out_idx = out + 52428800ull;

    // ===================== phase 1: conv units =====================
    while (true) {
        if (tid == 0) s_unit = (int)atomicAdd(&g_conv_ctr, 1u);
        __syncthreads();
        const int m = s_unit;
        if (m >= 800) break;
        const int c = m % 25;
        const int b = m / 25;

        if (tid < 49) sw[tid] = w7[c * 49 + tid];
        if (tid == 49) sbias = b7[c];
        if (tid == 50) {
            const float* w3c = w3 + c * 9;
            float Sc[3][3];
            #pragma unroll
            for (int a = 0; a < 3; a++) {
                float v0 = w3c[a*3+0], v1 = w3c[a*3+1], v2 = w3c[a*3+2];
                Sc[a][0] = v0 + v1;
                Sc[a][1] = v0 + v1 + v2;
                Sc[a][2] = v1 + v2;
            }
            #pragma unroll
            for (int cc = 0; cc < 3; cc++) {
                sWcat[0*3+cc] = Sc[0][cc] + Sc[1][cc];
                sWcat[1*3+cc] = Sc[0][cc] + Sc[1][cc] + Sc[2][cc];
                sWcat[2*3+cc] = Sc[1][cc] + Sc[2][cc];
            }
        }
        __syncthreads();

        const int cg   = tid & 63;
        const int band = tid >> 6;
        float gsum = 0.f;

        if (cg < 63) {
            float w[49];
            #pragma unroll
            for (int k = 0; k < 49; k++) w[k] = sw[k];
            const float bias = sbias;

            const int q0 = cg * 4;
            const bool  okL = (q0 > 0);
            const bool  okR = (q0 + 8 < 256);
            const int   offL = okL ? (q0 - 1) : 0;
            const int   offR = okR ? (q0 + 8) : 255;

            float wv1[4];
            #pragma unroll
            for (int t = 0; t < 4; t++) {
                int q   = q0 + t;
                int cat = (q == 0) ? 0 : ((q == 251) ? 2 : 1);
                wv1[t] = sWcat[1*3 + cat];
            }

            const int lo = band * 63;
            const float* __restrict__ xm = x + (size_t)m * 65536;

            float buf[10];
            {   // prologue: row lo-1
                const int  r   = lo - 1;
                const bool rok = (r >= 0);
                const float* __restrict__ row = xm + (rok ? r : 0) * 256;
                float  xl = row[offL];
                float4 v0 = *reinterpret_cast<const float4*>(row + q0);
                float4 v1 = *reinterpret_cast<const float4*>(row + q0 + 4);
                float  xr = row[offR];
                buf[0] = (rok && okL) ? xl : 0.f;
                buf[1] = rok ? v0.x : 0.f;  buf[2] = rok ? v0.y : 0.f;
                buf[3] = rok ? v0.z : 0.f;  buf[4] = rok ? v0.w : 0.f;
                buf[5] = rok ? v1.x : 0.f;  buf[6] = rok ? v1.y : 0.f;
                buf[7] = rok ? v1.z : 0.f;  buf[8] = rok ? v1.w : 0.f;
                buf[9] = (rok && okR) ? xr : 0.f;
            }

            float acc[7][4];
            #pragma unroll
            for (int s = 0; s < 7; s++)
                #pragma unroll
                for (int t = 0; t < 4; t++) acc[s][t] = 0.f;

            for (int it = 0; it < 10; ++it) {
                #pragma unroll
                for (int u = 0; u < 7; u++) {
                    const int r = lo - 1 + it * 7 + u;   // row in buf

                    // issue next-row loads (hidden under FMA block)
                    const int  rn   = r + 1;
                    const bool rokn = ((unsigned)rn < 256u);
                    const int  rcn  = rokn ? rn : 255;
                    const float* __restrict__ rowp = xm + rcn * 256;
                    float  nxl = rowp[offL];
                    float4 nv0 = *reinterpret_cast<const float4*>(rowp + q0);
                    float4 nv1 = *reinterpret_cast<const float4*>(rowp + q0 + 4);
                    float  nxr = rowp[offR];

                    // 196 FMAs on buf (row r)
                    #pragma unroll
                    for (int a = 0; a < 7; a++) {
                        const int s = (u - a + 7) % 7;
                        #pragma unroll
                        for (int dx = 0; dx < 7; dx++) {
                            const float wk = w[a * 7 + dx];
                            acc[s][0] = fmaf(buf[dx],     wk, acc[s][0]);
                            acc[s][1] = fmaf(buf[dx + 1], wk, acc[s][1]);
                            acc[s][2] = fmaf(buf[dx + 2], wk, acc[s][2]);
                            acc[s][3] = fmaf(buf[dx + 3], wk, acc[s][3]);
                        }
                    }

                    // retire out row i = r-5
                    {
                        const int  off   = it * 7 + u - 6;
                        const int  sret  = (u + 1) % 7;
                        const bool offok = (off >= 0) && (off <= 62);
                        const int  i     = lo + off;
                        const bool edge  = (i == 0) || (i == 251);

                        float wsv[4];
                        #pragma unroll
                        for (int t = 0; t < 4; t++) wsv[t] = wv1[t];
                        if (edge) {
                            const int rowcat = (i == 0) ? 0 : 2;
                            #pragma unroll
                            for (int t = 0; t < 4; t++) {
                                const int q = q0 + t;
                                const int colcat = (q == 0) ? 0 : ((q == 251) ? 2 : 1);
                                wsv[t] = sWcat[rowcat * 3 + colcat];
                            }
                        }
                        #pragma unroll
                        for (int t = 0; t < 4; t++) {
                            float h  = acc[sret][t] + bias;
                            float gl = fast_gelu(h);
                            float ws = offok ? wsv[t] : 0.f;
                            gsum = fmaf(gl, ws, gsum);
                            acc[sret][t] = 0.f;
                        }
                    }

                    // commit prefetch
                    buf[0] = (rokn && okL) ? nxl : 0.f;
                    buf[1] = rokn ? nv0.x : 0.f;  buf[2] = rokn ? nv0.y : 0.f;
                    buf[3] = rokn ? nv0.z : 0.f;  buf[4] = rokn ? nv0.w : 0.f;
                    buf[5] = rokn ? nv1.x : 0.f;  buf[6] = rokn ? nv1.y : 0.f;
                    buf[7] = rokn ? nv1.z : 0.f;  buf[8] = rokn ? nv1.w : 0.f;
                    buf[9] = (rokn && okR) ? nxr : 0.f;
                }
            }
        }

        sred[tid] = gsum;
        __syncthreads();
        #pragma unroll
        for (int ofs = 128; ofs > 0; ofs >>= 1) {
            if (tid < ofs) sred[tid] += sred[tid + ofs];
            __syncthreads();
        }
        if (tid == 0) {
            g_sums[m] = sred[0];
            __threadfence();
            unsigned v = atomicAdd(&g_batch_cnt[b], 1u);
            s_mlpb = (v == 24u) ? b : -1;
        }
        __syncthreads();

        // ---- inline per-batch MLP + stable top-k (this CTA completed batch) ----
        if (s_mlpb >= 0) {
            const int bb = s_mlpb;
            __threadfence();   // acquire g_sums written by other CTAs
            if (tid < 25)
                bs_g[tid] = g_sums[bb * 25 + tid] * (1.0f / 63504.0f);
            __syncthreads();
            if (tid < 50) {
                float v = fc1b[tid];
                #pragma unroll
                for (int cc = 0; cc < 25; cc++)
                    v = fmaf(bs_g[cc], fc1w[tid * 25 + cc], v);
                bs_hid[tid] = v > 0.f ? v : 0.f;
            }
            __syncthreads();
            if (tid < 25) {
                float z = fc2b[tid];
                #pragma unroll
                for (int j = 0; j < 50; j++)
                    z = fmaf(bs_hid[j], fc2w[tid * 50 + j], z);
                bs_s[tid] = 1.0f / (1.0f + expf(-z));
            }
            __syncthreads();
            if (tid < 25) {
                const float sv = bs_s[tid];
                int rank = 0;
                #pragma unroll
                for (int o = 0; o < 25; o++) {
                    float ov = bs_s[o];
                    rank += (ov > sv) || (ov == sv && o < tid);
                }
                const float s2 = sv * sv;
                g_chan[bb * 25 + rank]  = tid;
                g_gate[bb * 25 + rank]  = s2 / (s2 + 1e-8f);
                out_idx[bb * 25 + rank] = (float)tid;
                __threadfence();    // release rank/gate data
            }
            __syncthreads();
            if (tid == 0) g_batch_ready[bb] = 1;
        }
    }

    // ===================== phase 2: gather chunks =====================
    // 3200 chunks = 32 batches x (25 maps x 4 quarters), batch-ordered.
    while (true) {
        if (tid == 0) s_unit = (int)atomicAdd(&g_gather_ctr, 1u);
        __syncthreads();
        const int g = s_unit;
        if (g >= 3200) break;
        const int b     = g / 100;
        const int chunk = g % 100;
        const int r     = chunk >> 2;
        const int q     = chunk & 3;

        if (tid == 0) {
            while (g_batch_ready[b] == 0) __nanosleep(64);
        }
        __syncthreads();
        __threadfence();   // acquire gate/chan

        const int   ch = g_chan[b * 25 + r];
        const float gt = g_gate[b * 25 + r];

        const float4* __restrict__ src =
            reinterpret_cast<const float4*>(x + ((size_t)b * 25 + ch) * 65536);
        float* dbase;
        if (r < 10) dbase = out + ((size_t)b * 10 + r) * 65536;
        else        dbase = out + 20971520ull + ((size_t)b * 15 + (r - 10)) * 65536;
        float4* __restrict__ dst = reinterpret_cast<float4*>(dbase);

        const int base = q * 4096 + tid;   // 16384 f4 per map, 4 chunks
        #pragma unroll
        for (int half = 0; half < 2; half++) {
            float4 v[8];
            #pragma unroll
            for (int k = 0; k < 8; k++)
                v[k] = __ldcs(&src[base + (half * 8 + k) * 256]);
            #pragma unroll
            for (int k = 0; k < 8; k++) {
                v[k].x *= gt; v[k].y *= gt; v[k].z *= gt; v[k].w *= gt;
                __stcs(&dst[base + (half * 8 + k) * 256], v[k]);
            }
        }
    }

    // ===================== exit: last CTA resets queues =====================
    __syncthreads();
    if (tid == 0) {
        __threadfence();
        unsigned v = atomicAdd(&g_exit_ctr, 1u);
        if (v == gridDim.x - 1) {
            g_conv_ctr   = 0;
            g_gather_ctr = 0;
            g_exit_ctr   = 0;
            #pragma unroll
            for (int i = 0; i < 32; i++) {
                g_batch_cnt[i]   = 0;
                g_batch_ready[i] = 0;
            }
            __threadfence();
        }
    }
}

// =========================================================================
extern "C" void kernel_launch(void* const* d_in, const int* in_sizes, int n_in,
                              void* d_out, int out_size)
{
    const float* x    = (const float*)d_in[0];
    const float* w7   = (const float*)d_in[1];
    const float* b7   = (const float*)d_in[2];
    const float* w3   = (const float*)d_in[3];
    const float* fc1w = (const float*)d_in[4];
    const float* fc1b = (const float*)d_in[5];
    const float* fc2w = (const float*)d_in[6];
    const float* fc2b = (const float*)d_in[7];
    float* out = (float*)d_out;

    mega_kernel<<<296, 256>>>(x, w7, b7, w3, fc1w, fc1b, fc2w, fc2b, out);
}

// round 12
// speedup vs baseline: 1.5738x; 1.0036x over previous
#include <cuda_runtime.h>
#include <math.h>

// ---------------- device scratch (no allocations allowed) ----------------
static __device__ float         g_part[800 * 8];
static __device__ float         g_sums[800];
static __device__ float         g_gate[800];
static __device__ int           g_chan[800];
static __device__ unsigned int  g_conv_ctr   = 0;
static __device__ unsigned int  g_gather_ctr = 0;
static __device__ unsigned int  g_exit_ctr   = 0;
static __device__ unsigned int  g_map_cnt[800];
static __device__ unsigned int  g_batch_cnt[32];
static __device__ volatile int  g_batch_ready[32];

// Fast exact-form GELU: 0.5*h*(1+erf(h/sqrt(2))) with Abramowitz-Stegun
// 7.1.26 erf (max abs err ~1.5e-7).
__device__ __forceinline__ float fast_gelu(float h)
{
    const float az = fabsf(h) * 0.7071067811865476f;
    const float t  = __fdividef(1.0f, fmaf(0.3275911f, az, 1.0f));
    float p = fmaf(1.061405429f, t, -1.453152027f);
    p = fmaf(p, t, 1.421413741f);
    p = fmaf(p, t, -0.284496736f);
    p = fmaf(p, t, 0.254829592f);
    const float ex = __expf(-0.5f * h * h);
    float er = fmaf(-p * t, ex, 1.0f);
    er = copysignf(er, h);
    return 0.5f * h * (1.0f + er);
}

// Warp-local MLP + sigmoid + gate + stable top-k for one batch.
// sc: 80-float per-warp smem scratch. Release via per-lane fences + flag.
__device__ __forceinline__ void warp_mlp(int bb, int lane, float* sc,
                                         const float* __restrict__ fc1w,
                                         const float* __restrict__ fc1b,
                                         const float* __restrict__ fc2w,
                                         const float* __restrict__ fc2b,
                                         float* __restrict__ out_idx)
{
    __threadfence();    // acquire g_sums written by other warps
    if (lane < 25) sc[lane] = g_sums[bb * 25 + lane] * (1.0f / 63504.0f);
    __syncwarp();
    #pragma unroll
    for (int rep = 0; rep < 2; rep++) {
        const int j = lane + rep * 32;
        if (j < 50) {
            float v = __ldg(fc1b + j);
            #pragma unroll
            for (int cc = 0; cc < 25; cc++)
                v = fmaf(sc[cc], __ldg(fc1w + j * 25 + cc), v);
            sc[25 + j] = v > 0.f ? v : 0.f;
        }
    }
    __syncwarp();
    if (lane < 25) {
        float z = __ldg(fc2b + lane);
        #pragma unroll
        for (int j = 0; j < 50; j++)
            z = fmaf(sc[25 + j], __ldg(fc2w + lane * 50 + j), z);
        sc[lane] = 1.0f / (1.0f + expf(-z));   // s overwrites g region
    }
    __syncwarp();
    if (lane < 25) {
        const float sv = sc[lane];
        int rank = 0;
        #pragma unroll
        for (int o = 0; o < 25; o++) {
            const float ov = sc[o];
            rank += (ov > sv) || (ov == sv && o < lane);
        }
        const float s2 = sv * sv;
        g_chan[bb * 25 + rank]  = lane;
        g_gate[bb * 25 + rank]  = s2 / (s2 + 1e-8f);
        out_idx[bb * 25 + rank] = (float)lane;
        __threadfence();    // release before ready flag
    }
    __syncwarp();
    if (lane == 0) g_batch_ready[bb] = 1;
}

// =========================================================================
// Persistent warp-autonomous mega-kernel.
// Phase 1: 6400 conv warp-units (map x band x col-half), software-pipelined
//          dwconv7 + fast GELU + region-weighted sum; per-map fixed-order
//          finalize; per-batch warp-local MLP/top-k.
// Phase 2: 6400 gather warp-units (batch-ordered), gated on ready flags.
// No __syncthreads anywhere: warps overlap conv (fma-bound) with gather
// (DRAM-bound) at warp granularity.
// =========================================================================
__global__ __launch_bounds__(256, 2)
void mega_kernel(const float* __restrict__ x,
                 const float* __restrict__ w7,
                 const float* __restrict__ b7,
                 const float* __restrict__ w3,
                 const float* __restrict__ fc1w,
                 const float* __restrict__ fc1b,
                 const float* __restrict__ fc2w,
                 const float* __restrict__ fc2b,
                 float* __restrict__ out)
{
    __shared__ float wsch[8][80];
    const int lane = threadIdx.x & 31;
    const int wid  = threadIdx.x >> 5;
    float* sc = wsch[wid];
    float* __restrict__ out_idx = out + 52428800ull;

    // ===================== phase 1: conv warp-units =====================
    while (true) {
        int uc;
        if (lane == 0) uc = (int)atomicAdd(&g_conv_ctr, 1u);
        uc = __shfl_sync(0xffffffffu, uc, 0);
        if (uc >= 6400) break;

        const int m    = uc >> 3;       // map (batch-major order)
        const int sub  = uc & 7;
        const int band = sub >> 1;
        const int half = sub & 1;
        const int c    = m % 25;
        const int b    = m / 25;
        const int cg   = half * 32 + lane;   // 0..63, active < 63

        float gsum = 0.f;

        if (cg < 63) {
            // per-warp uniform weight loads (L1-resident after first touch)
            float w[49];
            #pragma unroll
            for (int k = 0; k < 49; k++) w[k] = __ldg(w7 + c * 49 + k);
            const float bias = __ldg(b7 + c);

            // interior-row region weights per output column
            float M0 = 0.f, M1 = 0.f, M2 = 0.f;
            #pragma unroll
            for (int a = 0; a < 3; a++) {
                const float v0 = __ldg(w3 + c * 9 + a * 3 + 0);
                const float v1 = __ldg(w3 + c * 9 + a * 3 + 1);
                const float v2 = __ldg(w3 + c * 9 + a * 3 + 2);
                M0 += v0 + v1; M1 += v0 + v1 + v2; M2 += v1 + v2;
            }
            const int q0 = cg * 4;
            float wv1[4];
            #pragma unroll
            for (int t = 0; t < 4; t++) {
                const int q   = q0 + t;
                const int cat = (q == 0) ? 0 : ((q == 251) ? 2 : 1);
                wv1[t] = (cat == 0) ? M0 : ((cat == 2) ? M2 : M1);
            }

            const bool okL  = (q0 > 0);
            const bool okR  = (q0 + 8 < 256);
            const int  offL = okL ? (q0 - 1) : 0;
            const int  offR = okR ? (q0 + 8) : 255;
            const int  lo   = band * 63;              // lo % 7 == 0
            const float* __restrict__ xm = x + (size_t)m * 65536;

            float buf[10];
            {   // prologue: row lo-1
                const int  r   = lo - 1;
                const bool rok = (r >= 0);
                const float* __restrict__ row = xm + (rok ? r : 0) * 256;
                float  xl = row[offL];
                float4 v0 = *reinterpret_cast<const float4*>(row + q0);
                float4 v1 = *reinterpret_cast<const float4*>(row + q0 + 4);
                float  xr = row[offR];
                buf[0] = (rok && okL) ? xl : 0.f;
                buf[1] = rok ? v0.x : 0.f;  buf[2] = rok ? v0.y : 0.f;
                buf[3] = rok ? v0.z : 0.f;  buf[4] = rok ? v0.w : 0.f;
                buf[5] = rok ? v1.x : 0.f;  buf[6] = rok ? v1.y : 0.f;
                buf[7] = rok ? v1.z : 0.f;  buf[8] = rok ? v1.w : 0.f;
                buf[9] = (rok && okR) ? xr : 0.f;
            }

            float acc[7][4];
            #pragma unroll
            for (int s = 0; s < 7; s++)
                #pragma unroll
                for (int t = 0; t < 4; t++) acc[s][t] = 0.f;

            for (int it = 0; it < 10; ++it) {
                #pragma unroll
                for (int u = 0; u < 7; u++) {
                    const int r = lo - 1 + it * 7 + u;   // row in buf

                    // issue next-row loads (hidden under FMA block)
                    const int  rn   = r + 1;
                    const bool rokn = ((unsigned)rn < 256u);
                    const int  rcn  = rokn ? rn : 255;
                    const float* __restrict__ rowp = xm + rcn * 256;
                    float  nxl = rowp[offL];
                    float4 nv0 = *reinterpret_cast<const float4*>(rowp + q0);
                    float4 nv1 = *reinterpret_cast<const float4*>(rowp + q0 + 4);
                    float  nxr = rowp[offR];

                    // 196 FMAs on buf (row r)
                    #pragma unroll
                    for (int a = 0; a < 7; a++) {
                        const int s = (u - a + 7) % 7;
                        #pragma unroll
                        for (int dx = 0; dx < 7; dx++) {
                            const float wk = w[a * 7 + dx];
                            acc[s][0] = fmaf(buf[dx],     wk, acc[s][0]);
                            acc[s][1] = fmaf(buf[dx + 1], wk, acc[s][1]);
                            acc[s][2] = fmaf(buf[dx + 2], wk, acc[s][2]);
                            acc[s][3] = fmaf(buf[dx + 3], wk, acc[s][3]);
                        }
                    }

                    // retire out row i = r-5, slot (u+1)%7
                    {
                        const int  off   = it * 7 + u - 6;
                        const int  sret  = (u + 1) % 7;
                        const bool offok = (off >= 0) && (off <= 62);
                        const int  i     = lo + off;
                        const bool edge  = (i == 0) || (i == 251);  // warp-uniform

                        float wsv[4];
                        #pragma unroll
                        for (int t = 0; t < 4; t++) wsv[t] = wv1[t];
                        if (edge) {
                            // cold path: 2 of 252 rows; recompute from w3
                            const int a0 = (i == 0) ? 0 : 1;
                            float C0 = 0.f, C1 = 0.f, C2 = 0.f;
                            #pragma unroll
                            for (int a = 0; a < 2; a++) {
                                const float v0 = __ldg(w3 + c * 9 + (a0 + a) * 3 + 0);
                                const float v1 = __ldg(w3 + c * 9 + (a0 + a) * 3 + 1);
                                const float v2 = __ldg(w3 + c * 9 + (a0 + a) * 3 + 2);
                                C0 += v0 + v1; C1 += v0 + v1 + v2; C2 += v1 + v2;
                            }
                            #pragma unroll
                            for (int t = 0; t < 4; t++) {
                                const int q   = q0 + t;
                                const int cat = (q == 0) ? 0 : ((q == 251) ? 2 : 1);
                                wsv[t] = (cat == 0) ? C0 : ((cat == 2) ? C2 : C1);
                            }
                        }
                        #pragma unroll
                        for (int t = 0; t < 4; t++) {
                            const float h  = acc[sret][t] + bias;
                            const float gl = fast_gelu(h);
                            const float ws = offok ? wsv[t] : 0.f;
                            gsum = fmaf(gl, ws, gsum);
                            acc[sret][t] = 0.f;
                        }
                    }

                    // commit prefetch
                    buf[0] = (rokn && okL) ? nxl : 0.f;
                    buf[1] = rokn ? nv0.x : 0.f;  buf[2] = rokn ? nv0.y : 0.f;
                    buf[3] = rokn ? nv0.z : 0.f;  buf[4] = rokn ? nv0.w : 0.f;
                    buf[5] = rokn ? nv1.x : 0.f;  buf[6] = rokn ? nv1.y : 0.f;
                    buf[7] = rokn ? nv1.z : 0.f;  buf[8] = rokn ? nv1.w : 0.f;
                    buf[9] = (rokn && okR) ? nxr : 0.f;
                }
            }
        }

        // warp reduce (fixed order -> deterministic)
        #pragma unroll
        for (int o = 16; o; o >>= 1)
            gsum += __shfl_xor_sync(0xffffffffu, gsum, o);

        int mlp_b = -1;
        if (lane == 0) {
            g_part[uc] = gsum;
            __threadfence();
            if (atomicAdd(&g_map_cnt[m], 1u) == 7u) {
                __threadfence();               // acquire other warps' partials
                float s = 0.f;
                #pragma unroll
                for (int k = 0; k < 8; k++) s += g_part[m * 8 + k];  // fixed order
                g_sums[m] = s;
                __threadfence();
                if (atomicAdd(&g_batch_cnt[b], 1u) == 24u) mlp_b = b;
            }
        }
        mlp_b = __shfl_sync(0xffffffffu, mlp_b, 0);
        if (mlp_b >= 0)
            warp_mlp(mlp_b, lane, sc, fc1w, fc1b, fc2w, fc2b, out_idx);
    }

    // ===================== phase 2: gather warp-units =====================
    // 6400 units = 32 batches x 25 maps x 8 octants, batch-ordered.
    while (true) {
        int g;
        if (lane == 0) g = (int)atomicAdd(&g_gather_ctr, 1u);
        g = __shfl_sync(0xffffffffu, g, 0);
        if (g >= 6400) break;
        const int b   = g / 200;
        const int rem = g % 200;
        const int r   = rem >> 3;
        const int oct = rem & 7;

        if (lane == 0) {
            while (g_batch_ready[b] == 0) __nanosleep(64);
        }
        __syncwarp();
        __threadfence();   // acquire gate/chan

        const int   ch = g_chan[b * 25 + r];
        const float gt = g_gate[b * 25 + r];

        const float4* __restrict__ src =
            reinterpret_cast<const float4*>(x + ((size_t)b * 25 + ch) * 65536);
        float* dbase;
        if (r < 10) dbase = out + ((size_t)b * 10 + r) * 65536;
        else        dbase = out + 20971520ull + ((size_t)b * 15 + (r - 10)) * 65536;
        float4* __restrict__ dst = reinterpret_cast<float4*>(dbase);

        const int base = oct * 2048 + lane;   // 2048 float4 per octant
        #pragma unroll
        for (int blk = 0; blk < 4; blk++) {
            float4 v[16];
            #pragma unroll
            for (int k = 0; k < 16; k++)
                v[k] = __ldcs(&src[base + (blk * 16 + k) * 32]);
            #pragma unroll
            for (int k = 0; k < 16; k++) {
                v[k].x *= gt; v[k].y *= gt; v[k].z *= gt; v[k].w *= gt;
                __stcs(&dst[base + (blk * 16 + k) * 32], v[k]);
            }
        }
    }

    // ===================== exit: last warp resets queues =====================
    {
        int is_last = 0;
        if (lane == 0) {
            __threadfence();
            unsigned v = atomicAdd(&g_exit_ctr, 1u);
            is_last = (v == gridDim.x * 8u - 1u);
        }
        is_last = __shfl_sync(0xffffffffu, is_last, 0);
        if (is_last) {
            for (int i = lane; i < 800; i += 32) g_map_cnt[i] = 0;
            g_batch_cnt[lane]   = 0;            // lane < 32
            g_batch_ready[lane] = 0;
            if (lane == 0) {
                g_conv_ctr   = 0;
                g_gather_ctr = 0;
                g_exit_ctr   = 0;
            }
            __threadfence();
        }
    }
}

// =========================================================================
extern "C" void kernel_launch(void* const* d_in, const int* in_sizes, int n_in,
                              void* d_out, int out_size)
{
    const float* x    = (const float*)d_in[0];
    const float* w7   = (const float*)d_in[1];
    const float* b7   = (const float*)d_in[2];
    const float* w3   = (const float*)d_in[3];
    const float* fc1w = (const float*)d_in[4];
    const float* fc1b = (const float*)d_in[5];
    const float* fc2w = (const float*)d_in[6];
    const float* fc2b = (const float*)d_in[7];
    float* out = (float*)d_out;

    mega_kernel<<<296, 256>>>(x, w7, b7, w3, fc1w, fc1b, fc2w, fc2b, out);
}